// round 1
// baseline (speedup 1.0000x reference)
#include <cuda_runtime.h>
#include <cstdint>

// ---------------------------------------------------------------------------
// Problem: N=8192, IN=256, HID=128
//   zp = ELU(z@W1+b1)@W2+b2 for z_mp, z_sc; L2-normalize rows
//   sim[i,j] = exp( dot(nA[i], nB[j]) / 0.2 )
//   rowS[i]=sum_j sim ; rowP[i]=sum_j sim*pos[i,j]
//   colS[j]=sum_i sim ; colP[j]=sum_i sim*pos[j,i]   (note transposed pos!)
//   ans[i] = 0.5*(-log(rowP/(rowS+eps)+eps)) + 0.5*(-log(colP/(colS+eps)+eps))
// Fully fused: sim never materialized. Deterministic (no float atomics):
// per-tile partials to global, fixed-order reduction pass.
// ---------------------------------------------------------------------------

#define NN 8192
#define INSZ 256
#define HID 128
#define NBLK 64   // NN / 128

// scratch (device globals: allocation-free)
__device__ float g_nAT[HID * NN];      // normalized proj(z_mp), [hid][N]
__device__ float g_nBT[HID * NN];      // normalized proj(z_sc), [hid][N]
__device__ float g_rowS[NBLK * NN];    // partial row sums, indexed [J][i]
__device__ float g_rowP[NBLK * NN];
__device__ float g_colS[NBLK * NN];    // partial col sums, indexed [I][j]
__device__ float g_colP[NBLK * NN];

// ---- packed fp32x2 helpers (Blackwell FFMA2 path, PTX-only) ----
__device__ __forceinline__ unsigned long long dup2(float a) {
    unsigned long long r;
    asm("mov.b64 %0, {%1, %1};" : "=l"(r) : "f"(a));
    return r;
}
__device__ __forceinline__ void fma2(unsigned long long& d,
                                     unsigned long long a,
                                     unsigned long long b) {
    asm("fma.rn.f32x2 %0, %1, %2, %0;" : "+l"(d) : "l"(a), "l"(b));
}
__device__ __forceinline__ float2 unpk(unsigned long long v) {
    float2 r;
    asm("mov.b64 {%0, %1}, %2;" : "=f"(r.x), "=f"(r.y) : "l"(v));
    return r;
}

// exp() on the FMA pipe (avoid MUFU EX2 throughput wall). |x| <= ~80.
__device__ __forceinline__ float fast_exp(float x) {
    float y = x * 1.4426950408889634f;     // log2(e)
    float t = y + 12582912.0f;             // round-to-nearest int (2^23+2^22)
    int   ti = __float_as_int(t);
    float n = t - 12582912.0f;
    float f = y - n;                        // f in [-0.5, 0.5]
    float p = 1.3333558146e-3f;
    p = fmaf(p, f, 9.6181291076e-3f);
    p = fmaf(p, f, 5.5504108664e-2f);
    p = fmaf(p, f, 2.4022650696e-1f);
    p = fmaf(p, f, 6.9314718056e-1f);
    p = fmaf(p, f, 1.0f);
    unsigned sb = ((unsigned)(ti - 0x4B400000 + 127)) << 23;  // 2^n bits
    return __uint_as_float(sb) * p;
}

// ---------------------------------------------------------------------------
// Kernel 1: projection + L2 norm, writes transposed [hid][N] outputs.
// grid = (64 row-blocks, 2 inputs), 256 threads.
// ---------------------------------------------------------------------------
#define ZS_STRIDE 68     // 64 + 4 (keeps float4 alignment, avoids conflicts)
#define HS_STRIDE 129

#define PROJ_SMEM_FLOATS (128*ZS_STRIDE + 64*128 + 128*HS_STRIDE + 128*128)
#define PROJ_SMEM_BYTES  (PROJ_SMEM_FLOATS * 4)

__global__ void __launch_bounds__(256, 1)
proj_kernel(const float* __restrict__ zA, const float* __restrict__ zB,
            const float* __restrict__ W1, const float* __restrict__ b1,
            const float* __restrict__ W2, const float* __restrict__ b2) {
    const float* z    = blockIdx.y ? zB : zA;
    float*       outT = blockIdx.y ? g_nBT : g_nAT;

    extern __shared__ float sm[];
    float* z_s  = sm;                          // [128 rows][ZS_STRIDE] (r-major, k inner)
    float* w_s  = z_s + 128 * ZS_STRIDE;       // [64 k][128 c]
    float* h_s  = w_s + 64 * 128;              // [128 c][HS_STRIDE] (c-major = k-major for B)
    float* w2_s = h_s + 128 * HS_STRIDE;       // [128 k][128 c]

    const int tid = threadIdx.x;
    const int tx = tid & 15, ty = tid >> 4;
    const int R0 = ty * 8, C0 = tx * 8;
    const int rowBlk = blockIdx.x;
    const float* zblk = z + (size_t)rowBlk * 128 * INSZ;

    // preload W2 (used in phase B)
    #pragma unroll
    for (int it = 0; it < 16; ++it) {
        int e = it * 256 + tid;
        ((float4*)w2_s)[e] = ((const float4*)W2)[e];
    }

    // ---- phase A: H = ELU(Z @ W1 + b1) ----
    unsigned long long acc[8][4];
    #pragma unroll
    for (int i = 0; i < 8; ++i)
        #pragma unroll
        for (int jp = 0; jp < 4; ++jp) acc[i][jp] = 0ull;

    for (int kc = 0; kc < 4; ++kc) {
        __syncthreads();
        // z chunk -> z_s[r][k], coalesced global reads
        #pragma unroll
        for (int it = 0; it < 8; ++it) {
            int e = it * 256 + tid;          // 2048 float4
            int r = e >> 4, k4 = (e & 15) * 4;
            float4 v = *(const float4*)&zblk[r * INSZ + kc * 64 + k4];
            *(float4*)&z_s[r * ZS_STRIDE + k4] = v;
        }
        // W1 chunk -> w_s[k][c]
        #pragma unroll
        for (int it = 0; it < 8; ++it) {
            int e = it * 256 + tid;          // 2048 float4
            int c4 = (e & 31) * 4, k = e >> 5;
            float4 v = *(const float4*)&W1[(size_t)(kc * 64 + k) * HID + c4];
            *(float4*)&w_s[k * 128 + c4] = v;
        }
        __syncthreads();

        #pragma unroll 4
        for (int k = 0; k < 64; ++k) {
            ulonglong2 b0 = *(const ulonglong2*)&w_s[k * 128 + C0];
            ulonglong2 b1v = *(const ulonglong2*)&w_s[k * 128 + C0 + 4];
            #pragma unroll
            for (int i = 0; i < 8; ++i) {
                unsigned long long ad = dup2(z_s[(R0 + i) * ZS_STRIDE + k]);
                fma2(acc[i][0], ad, b0.x);
                fma2(acc[i][1], ad, b0.y);
                fma2(acc[i][2], ad, b1v.x);
                fma2(acc[i][3], ad, b1v.y);
            }
        }
    }

    // bias + ELU -> h_s[c][r]
    float b1c[8];
    #pragma unroll
    for (int j = 0; j < 8; ++j) b1c[j] = b1[C0 + j];
    #pragma unroll
    for (int i = 0; i < 8; ++i) {
        #pragma unroll
        for (int jp = 0; jp < 4; ++jp) {
            float2 v = unpk(acc[i][jp]);
            float x0 = v.x + b1c[2 * jp];
            float x1 = v.y + b1c[2 * jp + 1];
            x0 = (x0 > 0.0f) ? x0 : (fast_exp(fmaxf(x0, -30.0f)) - 1.0f);
            x1 = (x1 > 0.0f) ? x1 : (fast_exp(fmaxf(x1, -30.0f)) - 1.0f);
            h_s[(C0 + 2 * jp)     * HS_STRIDE + R0 + i] = x0;
            h_s[(C0 + 2 * jp + 1) * HS_STRIDE + R0 + i] = x1;
        }
    }
    __syncthreads();

    // ---- phase B: P = H @ W2 + b2 ----
    #pragma unroll
    for (int i = 0; i < 8; ++i)
        #pragma unroll
        for (int jp = 0; jp < 4; ++jp) acc[i][jp] = 0ull;

    #pragma unroll 4
    for (int k = 0; k < 128; ++k) {
        ulonglong2 b0 = *(const ulonglong2*)&w2_s[k * 128 + C0];
        ulonglong2 b1v = *(const ulonglong2*)&w2_s[k * 128 + C0 + 4];
        #pragma unroll
        for (int i = 0; i < 8; ++i) {
            unsigned long long ad = dup2(h_s[k * HS_STRIDE + R0 + i]);
            fma2(acc[i][0], ad, b0.x);
            fma2(acc[i][1], ad, b0.y);
            fma2(acc[i][2], ad, b1v.x);
            fma2(acc[i][3], ad, b1v.y);
        }
    }

    float b2c[8];
    #pragma unroll
    for (int j = 0; j < 8; ++j) b2c[j] = b2[C0 + j];

    float x[8][8];
    float ss[8];
    #pragma unroll
    for (int i = 0; i < 8; ++i) {
        float s = 0.0f;
        #pragma unroll
        for (int jp = 0; jp < 4; ++jp) {
            float2 v = unpk(acc[i][jp]);
            float x0 = v.x + b2c[2 * jp];
            float x1 = v.y + b2c[2 * jp + 1];
            x[i][2 * jp] = x0;
            x[i][2 * jp + 1] = x1;
            s = fmaf(x0, x0, s);
            s = fmaf(x1, x1, s);
        }
        ss[i] = s;
    }
    // reduce sum-of-squares across tx (lanes 0-15 / 16-31 half-warps)
    #pragma unroll
    for (int m = 1; m < 16; m <<= 1)
        #pragma unroll
        for (int i = 0; i < 8; ++i)
            ss[i] += __shfl_xor_sync(0xffffffffu, ss[i], m);

    #pragma unroll
    for (int i = 0; i < 8; ++i) {
        float inv = 1.0f / fmaxf(sqrtf(ss[i]), 1e-12f);
        int gRow = rowBlk * 128 + R0 + i;
        #pragma unroll
        for (int j = 0; j < 8; ++j)
            outT[(size_t)(C0 + j) * NN + gRow] = x[i][j] * inv;
    }
}

// ---------------------------------------------------------------------------
// Kernel 2: fused 128x128 sim tile: GEMM (K=128) + exp + 4 reductions.
// grid = (J=64, I=64), 256 threads, one CTA per tile.
// ---------------------------------------------------------------------------
#define SIM_SMEM_FLOATS (16384 + 16384 + 4096)
#define SIM_SMEM_BYTES  (SIM_SMEM_FLOATS * 4)

__global__ void __launch_bounds__(256, 1)
sim_tile_kernel(const int* __restrict__ pos) {
    const int J = blockIdx.x, I = blockIdx.y;
    extern __shared__ float sm[];
    float* a_s = sm;             // [k][r] 128x128
    float* b_s = sm + 16384;     // [k][c] 128x128
    float* red = sm + 32768;     // [16][128] x 2

    const int tid = threadIdx.x;
    const int tx = tid & 15, ty = tid >> 4;
    const int R0 = ty * 8, C0 = tx * 8;

    // load tiles (coalesced; rows contiguous in transposed storage)
    #pragma unroll
    for (int it = 0; it < 16; ++it) {
        int e = it * 256 + tid;            // float4 index
        int k = e >> 5, r4 = (e & 31) * 4;
        *(float4*)&a_s[k * 128 + r4] = *(const float4*)&g_nAT[(size_t)k * NN + I * 128 + r4];
        *(float4*)&b_s[k * 128 + r4] = *(const float4*)&g_nBT[(size_t)k * NN + J * 128 + r4];
    }
    __syncthreads();

    unsigned long long acc[8][4];
    #pragma unroll
    for (int i = 0; i < 8; ++i)
        #pragma unroll
        for (int jp = 0; jp < 4; ++jp) acc[i][jp] = 0ull;

    #pragma unroll 8
    for (int k = 0; k < 128; ++k) {
        float4 a0 = *(const float4*)&a_s[k * 128 + R0];
        float4 a1 = *(const float4*)&a_s[k * 128 + R0 + 4];
        ulonglong2 b0 = *(const ulonglong2*)&b_s[k * 128 + C0];
        ulonglong2 b1v = *(const ulonglong2*)&b_s[k * 128 + C0 + 4];
        float av[8] = {a0.x, a0.y, a0.z, a0.w, a1.x, a1.y, a1.z, a1.w};
        #pragma unroll
        for (int i = 0; i < 8; ++i) {
            unsigned long long ad = dup2(av[i]);
            fma2(acc[i][0], ad, b0.x);
            fma2(acc[i][1], ad, b0.y);
            fma2(acc[i][2], ad, b1v.x);
            fma2(acc[i][3], ad, b1v.y);
        }
    }

    // exp(cos / 0.2)
    float ex[8][8];
    #pragma unroll
    for (int i = 0; i < 8; ++i)
        #pragma unroll
        for (int jp = 0; jp < 4; ++jp) {
            float2 v = unpk(acc[i][jp]);
            ex[i][2 * jp]     = fast_exp(v.x * 5.0f);
            ex[i][2 * jp + 1] = fast_exp(v.y * 5.0f);
        }

    const int giBase = I * 128 + R0;
    const int gjBase = J * 128 + C0;

    // row direction (mp): pos[i, j]
    float rowS[8], rowP[8];
    #pragma unroll
    for (int i = 0; i < 8; ++i) {
        size_t base = (size_t)(giBase + i) * NN + gjBase;
        int4 p0 = *(const int4*)&pos[base];
        int4 p1 = *(const int4*)&pos[base + 4];
        int pv[8] = {p0.x, p0.y, p0.z, p0.w, p1.x, p1.y, p1.z, p1.w};
        float s = 0.0f, q = 0.0f;
        #pragma unroll
        for (int j = 0; j < 8; ++j) {
            s += ex[i][j];
            if (pv[j]) q += ex[i][j];
        }
        rowS[i] = s; rowP[i] = q;
    }
    // col direction (sc): pos[j, i]  (contiguous in i)
    float colS[8], colP[8];
    #pragma unroll
    for (int j = 0; j < 8; ++j) {
        size_t base = (size_t)(gjBase + j) * NN + giBase;
        int4 p0 = *(const int4*)&pos[base];
        int4 p1 = *(const int4*)&pos[base + 4];
        int pv[8] = {p0.x, p0.y, p0.z, p0.w, p1.x, p1.y, p1.z, p1.w};
        float s = 0.0f, q = 0.0f;
        #pragma unroll
        for (int i = 0; i < 8; ++i) {
            s += ex[i][j];
            if (pv[i]) q += ex[i][j];
        }
        colS[j] = s; colP[j] = q;
    }

    // reduce rows across tx (butterfly within 16-lane halves)
    #pragma unroll
    for (int m = 1; m < 16; m <<= 1)
        #pragma unroll
        for (int i = 0; i < 8; ++i) {
            rowS[i] += __shfl_xor_sync(0xffffffffu, rowS[i], m);
            rowP[i] += __shfl_xor_sync(0xffffffffu, rowP[i], m);
        }
    if (tx == 0) {
        #pragma unroll
        for (int i = 0; i < 8; ++i) {
            g_rowS[(size_t)J * NN + giBase + i] = rowS[i];
            g_rowP[(size_t)J * NN + giBase + i] = rowP[i];
        }
    }

    // reduce cols across ty via smem
    float* redS = red;
    float* redP = red + 2048;
    #pragma unroll
    for (int j = 0; j < 8; ++j) {
        redS[ty * 128 + C0 + j] = colS[j];
        redP[ty * 128 + C0 + j] = colP[j];
    }
    __syncthreads();
    if (tid < 128) {
        float s = 0.0f, q = 0.0f;
        #pragma unroll
        for (int t = 0; t < 16; ++t) {
            s += redS[t * 128 + tid];
            q += redP[t * 128 + tid];
        }
        g_colS[(size_t)I * NN + J * 128 + tid] = s;
        g_colP[(size_t)I * NN + J * 128 + tid] = q;
    }
}

// ---------------------------------------------------------------------------
// Kernel 3: deterministic final reduction over the 64 tile-partials.
// ---------------------------------------------------------------------------
__global__ void finish_kernel(float* __restrict__ out) {
    int i = blockIdx.x * 256 + threadIdx.x;
    if (i >= NN) return;
    float rs = 0.0f, rp = 0.0f, cs = 0.0f, cp = 0.0f;
    #pragma unroll 8
    for (int t = 0; t < NBLK; ++t) {
        rs += g_rowS[(size_t)t * NN + i];
        rp += g_rowP[(size_t)t * NN + i];
        cs += g_colS[(size_t)t * NN + i];
        cp += g_colP[(size_t)t * NN + i];
    }
    float mp = rp / (rs + 1e-8f);
    float sc = cp / (cs + 1e-8f);
    float ans = 0.5f * (-logf(mp + 1e-8f)) + 0.5f * (-logf(sc + 1e-8f));
    if (isnan(ans) || isinf(ans)) ans = 0.0f;
    out[i] = ans;
}

// ---------------------------------------------------------------------------
extern "C" void kernel_launch(void* const* d_in, const int* in_sizes, int n_in,
                              void* d_out, int out_size) {
    const float* z_mp = (const float*)d_in[0];
    const float* z_sc = (const float*)d_in[1];
    const float* W1   = (const float*)d_in[2];
    const float* b1   = (const float*)d_in[3];
    const float* W2   = (const float*)d_in[4];
    const float* b2   = (const float*)d_in[5];
    const int*   pos  = (const int*)d_in[6];
    float* out = (float*)d_out;

    cudaFuncSetAttribute(proj_kernel, cudaFuncAttributeMaxDynamicSharedMemorySize,
                         PROJ_SMEM_BYTES);
    cudaFuncSetAttribute(sim_tile_kernel, cudaFuncAttributeMaxDynamicSharedMemorySize,
                         SIM_SMEM_BYTES);

    proj_kernel<<<dim3(64, 2), 256, PROJ_SMEM_BYTES>>>(z_mp, z_sc, W1, b1, W2, b2);
    sim_tile_kernel<<<dim3(64, 64), 256, SIM_SMEM_BYTES>>>(pos);
    finish_kernel<<<32, 256>>>(out);
}

// round 4
// speedup vs baseline: 1.6081x; 1.6081x over previous
#include <cuda_runtime.h>
#include <cuda_bf16.h>
#include <cstdint>

#define NN 8192
#define INSZ 256
#define HID 128
#define NBLK 64

// ---------------- device global scratch (allocation-free) ----------------
__device__ __align__(256) __nv_bfloat16 g_Ahi[NN * HID];
__device__ __align__(256) __nv_bfloat16 g_Alo[NN * HID];
__device__ __align__(256) __nv_bfloat16 g_Bhi[NN * HID];
__device__ __align__(256) __nv_bfloat16 g_Blo[NN * HID];
__device__ unsigned g_packed[NN * 256];    // pos bits: [r][c/32]  (pos[r][c])
__device__ float g_rowS[NBLK * NN];        // [J][i]
__device__ float g_rowP[NBLK * NN];
__device__ float g_colS[NBLK * NN];        // [I][j]
__device__ float g_colP[NBLK * NN];

// ---------------- helpers ----------------
__device__ __forceinline__ uint32_t smem_u32(const void* p) {
    uint32_t a;
    asm("{ .reg .u64 t; cvta.to.shared.u64 t, %1; cvt.u32.u64 %0, t; }" : "=r"(a) : "l"(p));
    return a;
}
__device__ __forceinline__ float ex2f(float x) {
    float y; asm("ex2.approx.ftz.f32 %0, %1;" : "=f"(y) : "f"(x)); return y;
}
__device__ __forceinline__ void ldsm4(uint32_t a, uint32_t& r0, uint32_t& r1,
                                      uint32_t& r2, uint32_t& r3) {
    asm volatile("ldmatrix.sync.aligned.m8n8.x4.shared.b16 {%0,%1,%2,%3}, [%4];"
                 : "=r"(r0), "=r"(r1), "=r"(r2), "=r"(r3) : "r"(a));
}
__device__ __forceinline__ void mma16816(float* d, const uint32_t* a, const uint32_t* b) {
    asm volatile("mma.sync.aligned.m16n8k16.row.col.f32.bf16.bf16.f32 "
                 "{%0,%1,%2,%3}, {%4,%5,%6,%7}, {%8,%9}, {%0,%1,%2,%3};"
                 : "+f"(d[0]), "+f"(d[1]), "+f"(d[2]), "+f"(d[3])
                 : "r"(a[0]), "r"(a[1]), "r"(a[2]), "r"(a[3]), "r"(b[0]), "r"(b[1]));
}
__device__ __forceinline__ void cp16(uint32_t dst, const void* src) {
    asm volatile("cp.async.cg.shared.global [%0], [%1], 16;" :: "r"(dst), "l"(src));
}
__device__ __forceinline__ void cp_commit_wait() {
    asm volatile("cp.async.commit_group;\n\tcp.async.wait_group 0;" ::: "memory");
}
__device__ __forceinline__ unsigned long long dup2(float a) {
    unsigned long long r; asm("mov.b64 %0, {%1, %1};" : "=l"(r) : "f"(a)); return r;
}
__device__ __forceinline__ void fma2(unsigned long long& d, unsigned long long a,
                                     unsigned long long b) {
    asm("fma.rn.f32x2 %0, %1, %2, %0;" : "+l"(d) : "l"(a), "l"(b));
}
__device__ __forceinline__ float2 unpk(unsigned long long v) {
    float2 r; asm("mov.b64 {%0, %1}, %2;" : "=f"(r.x), "=f"(r.y) : "l"(v)); return r;
}

// ---------------------------------------------------------------------------
// Kernel P: pack pos rows into bitmasks (one coalesced 256MB read)
// ---------------------------------------------------------------------------
__global__ void __launch_bounds__(256) pack_kernel(const int* __restrict__ pos) {
    int gw = (blockIdx.x * 256 + threadIdx.x) >> 5;   // 0..65535
    int lane = threadIdx.x & 31;
    int br = gw >> 8, bc = gw & 255;
    int r0 = br * 32, c0 = bc * 32;
    unsigned myw = 0;
    #pragma unroll 4
    for (int k = 0; k < 32; ++k) {
        int v = pos[(size_t)(r0 + k) * NN + c0 + lane];
        unsigned m = __ballot_sync(0xffffffffu, v != 0);
        if (lane == k) myw = m;
    }
    g_packed[(size_t)(r0 + lane) * 256 + bc] = myw;
}

// ---------------------------------------------------------------------------
// Kernel 1: projection + L2 norm + bf16 hi/lo split (A pre-scaled 5*log2e)
// ---------------------------------------------------------------------------
#define ZS 68
#define HS 66
#define PROJ_SMEM_FLOATS (64 * ZS + 64 * 128)
#define PROJ_SMEM_BYTES  (PROJ_SMEM_FLOATS * 4)

__global__ void __launch_bounds__(256, 2)
proj_kernel(const float* __restrict__ zA, const float* __restrict__ zB,
            const float* __restrict__ W1, const float* __restrict__ b1,
            const float* __restrict__ W2, const float* __restrict__ b2) {
    const bool isA = (blockIdx.y == 0);
    const float* z = isA ? zA : zB;
    __nv_bfloat16* hiDst = isA ? g_Ahi : g_Bhi;
    __nv_bfloat16* loDst = isA ? g_Alo : g_Blo;

    extern __shared__ float sm[];
    float* z_s = sm;                 // [64][ZS]
    float* w_s = sm + 64 * ZS;       // [64][128]
    float* h_s = sm;                 // [128][HS] (aliases after phase A)

    const int tid = threadIdx.x;
    const int tx = tid & 15, ty = tid >> 4;
    const int R0 = ty * 4, C0 = tx * 8;
    const int blk = blockIdx.x;
    const float* zblk = z + (size_t)blk * 64 * INSZ;

    unsigned long long acc[4][4];
    #pragma unroll
    for (int i = 0; i < 4; ++i)
        #pragma unroll
        for (int jp = 0; jp < 4; ++jp) acc[i][jp] = 0ull;

    for (int kc = 0; kc < 4; ++kc) {
        __syncthreads();
        #pragma unroll
        for (int it = 0; it < 4; ++it) {
            int e = it * 256 + tid;
            int r = e >> 4, k4 = (e & 15) * 4;
            float4 v = *(const float4*)&zblk[r * INSZ + kc * 64 + k4];
            *(float4*)&z_s[r * ZS + k4] = v;
        }
        #pragma unroll
        for (int it = 0; it < 8; ++it) {
            int e = it * 256 + tid;
            int c4 = (e & 31) * 4, k = e >> 5;
            float4 v = *(const float4*)&W1[(size_t)(kc * 64 + k) * HID + c4];
            *(float4*)&w_s[k * 128 + c4] = v;
        }
        __syncthreads();
        #pragma unroll 4
        for (int k = 0; k < 64; ++k) {
            ulonglong2 bb0 = *(const ulonglong2*)&w_s[k * 128 + C0];
            ulonglong2 bb1 = *(const ulonglong2*)&w_s[k * 128 + C0 + 4];
            #pragma unroll
            for (int i = 0; i < 4; ++i) {
                unsigned long long ad = dup2(z_s[(R0 + i) * ZS + k]);
                fma2(acc[i][0], ad, bb0.x);
                fma2(acc[i][1], ad, bb0.y);
                fma2(acc[i][2], ad, bb1.x);
                fma2(acc[i][3], ad, bb1.y);
            }
        }
    }
    __syncthreads();

    float b1c[8];
    #pragma unroll
    for (int j = 0; j < 8; ++j) b1c[j] = b1[C0 + j];
    #pragma unroll
    for (int i = 0; i < 4; ++i) {
        #pragma unroll
        for (int jp = 0; jp < 4; ++jp) {
            float2 v = unpk(acc[i][jp]);
            float x0 = v.x + b1c[2 * jp];
            float x1 = v.y + b1c[2 * jp + 1];
            x0 = (x0 > 0.0f) ? x0 : (ex2f(fmaxf(x0, -30.0f) * 1.4426950408889634f) - 1.0f);
            x1 = (x1 > 0.0f) ? x1 : (ex2f(fmaxf(x1, -30.0f) * 1.4426950408889634f) - 1.0f);
            h_s[(C0 + 2 * jp)     * HS + R0 + i] = x0;
            h_s[(C0 + 2 * jp + 1) * HS + R0 + i] = x1;
        }
    }
    __syncthreads();

    #pragma unroll
    for (int i = 0; i < 4; ++i)
        #pragma unroll
        for (int jp = 0; jp < 4; ++jp) acc[i][jp] = 0ull;

    #pragma unroll 4
    for (int k = 0; k < 128; ++k) {
        ulonglong2 bb0 = *(const ulonglong2*)&W2[(size_t)k * HID + C0];
        ulonglong2 bb1 = *(const ulonglong2*)&W2[(size_t)k * HID + C0 + 4];
        #pragma unroll
        for (int i = 0; i < 4; ++i) {
            unsigned long long ad = dup2(h_s[k * HS + R0 + i]);
            fma2(acc[i][0], ad, bb0.x);
            fma2(acc[i][1], ad, bb0.y);
            fma2(acc[i][2], ad, bb1.x);
            fma2(acc[i][3], ad, bb1.y);
        }
    }

    float b2c[8];
    #pragma unroll
    for (int j = 0; j < 8; ++j) b2c[j] = b2[C0 + j];

    float x[4][8], ss[4];
    #pragma unroll
    for (int i = 0; i < 4; ++i) {
        float s = 0.0f;
        #pragma unroll
        for (int jp = 0; jp < 4; ++jp) {
            float2 v = unpk(acc[i][jp]);
            float x0 = v.x + b2c[2 * jp];
            float x1 = v.y + b2c[2 * jp + 1];
            x[i][2 * jp] = x0; x[i][2 * jp + 1] = x1;
            s = fmaf(x0, x0, s); s = fmaf(x1, x1, s);
        }
        ss[i] = s;
    }
    #pragma unroll
    for (int m = 1; m < 16; m <<= 1)
        #pragma unroll
        for (int i = 0; i < 4; ++i)
            ss[i] += __shfl_xor_sync(0xffffffffu, ss[i], m);

    const float scl = isA ? 7.2134752044448170f : 1.0f;   // 5 * log2(e) on A
    union { __nv_bfloat16 b[8]; uint4 u; } hv, lv;
    #pragma unroll
    for (int i = 0; i < 4; ++i) {
        float inv = scl / fmaxf(sqrtf(ss[i]), 1e-12f);
        int gRow = blk * 64 + R0 + i;
        #pragma unroll
        for (int j = 0; j < 8; ++j) {
            float v = x[i][j] * inv;
            hv.b[j] = __float2bfloat16(v);
            lv.b[j] = __float2bfloat16(v - __bfloat162float(hv.b[j]));
        }
        *(uint4*)&hiDst[(size_t)gRow * HID + C0] = hv.u;
        *(uint4*)&loDst[(size_t)gRow * HID + C0] = lv.u;
    }
}

// ---------------------------------------------------------------------------
// Kernel 2: fused sim tile via mma.sync bf16 (hi/lo split), register epilogue.
// ---------------------------------------------------------------------------
#define SM_A0 0
#define SM_A1 32768
#define SM_B0 65536
#define SM_B1 98304
#define SM_POSR 131072
#define SM_POSC (131072 + 2048)
#define SM_ROWS 0
#define SM_ROWP 1024
#define SM_COLS 2048
#define SM_COLP 4096
#define SIM_SMEM_BYTES (131072 + 4096)

__global__ void __launch_bounds__(256, 1) sim_kernel() {
    const int J = blockIdx.x, I = blockIdx.y;
    extern __shared__ char smc[];
    const uint32_t sb = smem_u32(smc);
    const int tid = threadIdx.x;
    const int lane = tid & 31, wid = tid >> 5;
    const int wm = wid & 3, wn = wid >> 2;

    // ---- async-load 4 operand tiles (swizzled: chunk c -> c ^ (r&7)) ----
    {
        const __nv_bfloat16* srcs[4] = {
            g_Ahi + (size_t)I * 128 * HID, g_Alo + (size_t)I * 128 * HID,
            g_Bhi + (size_t)J * 128 * HID, g_Blo + (size_t)J * 128 * HID };
        const int dsto[4] = { SM_A0, SM_A1, SM_B0, SM_B1 };
        #pragma unroll
        for (int t = 0; t < 4; ++t) {
            const uint4* src = (const uint4*)srcs[t];
            #pragma unroll
            for (int it = 0; it < 8; ++it) {
                int e = it * 256 + tid;
                int r = e >> 4, c = e & 15;
                cp16(sb + dsto[t] + r * 256 + ((c ^ (r & 7)) << 4), src + e);
            }
        }
    }
    // ---- preload pos bitmask words (both orientations come from g_packed!) ----
    // row term needs pos[i][j]; col term needs pos[j][i] (reference multiplies
    // sc2mp[j,i] * pos[j,i]) -> also a ROW of pos, with i/j swapped indexing.
    unsigned* posR = (unsigned*)(smc + SM_POSR);
    unsigned* posC = (unsigned*)(smc + SM_POSC);
    #pragma unroll
    for (int e = tid; e < 512; e += 256) {
        int loc = e >> 2, w = e & 3;
        posR[e] = g_packed[(size_t)(I * 128 + loc) * 256 + J * 4 + w];
        posC[e] = g_packed[(size_t)(J * 128 + loc) * 256 + I * 4 + w];
    }
    cp_commit_wait();
    __syncthreads();

    // ---- MMA mainloop: 3 split passes (AhiBhi + AhiBlo + AloBhi) ----
    float d[2][8][4];
    #pragma unroll
    for (int mt = 0; mt < 2; ++mt)
        #pragma unroll
        for (int nt = 0; nt < 8; ++nt)
            #pragma unroll
            for (int k = 0; k < 4; ++k) d[mt][nt][k] = 0.0f;

    const int aOff[3] = { SM_A0, SM_A0, SM_A1 };
    const int bOff[3] = { SM_B0, SM_B1, SM_B0 };

    #pragma unroll 1
    for (int s = 0; s < 3; ++s) {
        const uint32_t aB = sb + aOff[s];
        const uint32_t bB = sb + bOff[s];
        #pragma unroll
        for (int ks = 0; ks < 8; ++ks) {
            uint32_t af[2][4];
            #pragma unroll
            for (int mt = 0; mt < 2; ++mt) {
                int row = wm * 32 + mt * 16 + (lane & 15);
                int ch  = ks * 2 + (lane >> 4);
                ldsm4(aB + row * 256 + ((ch ^ (row & 7)) << 4),
                      af[mt][0], af[mt][1], af[mt][2], af[mt][3]);
            }
            uint32_t bf[8][2];
            #pragma unroll
            for (int np = 0; np < 4; ++np) {
                int l = lane & 7, g = lane >> 3;
                int row = wn * 64 + np * 16 + ((g >> 1) << 3) + l;
                int ch  = ks * 2 + (g & 1);
                ldsm4(bB + row * 256 + ((ch ^ (row & 7)) << 4),
                      bf[2 * np][0], bf[2 * np][1], bf[2 * np + 1][0], bf[2 * np + 1][1]);
            }
            #pragma unroll
            for (int mt = 0; mt < 2; ++mt)
                #pragma unroll
                for (int nt = 0; nt < 8; ++nt)
                    mma16816(d[mt][nt], af[mt], bf[nt]);
        }
    }
    __syncthreads();   // tiles no longer needed; smem reused for reductions

    // ---- epilogue ----
    #pragma unroll
    for (int mt = 0; mt < 2; ++mt)
        #pragma unroll
        for (int nt = 0; nt < 8; ++nt)
            #pragma unroll
            for (int k = 0; k < 4; ++k)
                d[mt][nt][k] = ex2f(d[mt][nt][k]);

    float* rowSsm = (float*)(smc + SM_ROWS);
    float* rowPsm = (float*)(smc + SM_ROWP);
    float* colSsm = (float*)(smc + SM_COLS);
    float* colPsm = (float*)(smc + SM_COLP);

    #pragma unroll
    for (int mt = 0; mt < 2; ++mt) {
        #pragma unroll
        for (int h = 0; h < 2; ++h) {
            int iloc = wm * 32 + mt * 16 + (lane >> 2) + h * 8;
            unsigned w0 = posR[iloc * 4 + wn * 2];
            unsigned w1 = posR[iloc * 4 + wn * 2 + 1];
            float s = 0.0f, p = 0.0f;
            #pragma unroll
            for (int nt = 0; nt < 8; ++nt) {
                unsigned w = (nt < 4) ? w0 : w1;
                #pragma unroll
                for (int b = 0; b < 2; ++b) {
                    float e = d[mt][nt][h * 2 + b];
                    s += e;
                    int bit = (nt & 3) * 8 + (lane & 3) * 2 + b;
                    if ((w >> bit) & 1u) p += e;
                }
            }
            s += __shfl_xor_sync(0xffffffffu, s, 1);
            s += __shfl_xor_sync(0xffffffffu, s, 2);
            p += __shfl_xor_sync(0xffffffffu, p, 1);
            p += __shfl_xor_sync(0xffffffffu, p, 2);
            if ((lane & 3) == 0) {
                rowSsm[wn * 128 + iloc] = s;
                rowPsm[wn * 128 + iloc] = p;
            }
        }
    }

    #pragma unroll
    for (int nt = 0; nt < 8; ++nt) {
        #pragma unroll
        for (int b = 0; b < 2; ++b) {
            int jloc = wn * 64 + nt * 8 + (lane & 3) * 2 + b;
            unsigned w = posC[jloc * 4 + wm];
            float s = 0.0f, p = 0.0f;
            #pragma unroll
            for (int mt = 0; mt < 2; ++mt)
                #pragma unroll
                for (int h = 0; h < 2; ++h) {
                    float e = d[mt][nt][h * 2 + b];
                    s += e;
                    int bit = mt * 16 + h * 8 + (lane >> 2);
                    if ((w >> bit) & 1u) p += e;
                }
            s += __shfl_xor_sync(0xffffffffu, s, 4);
            s += __shfl_xor_sync(0xffffffffu, s, 8);
            s += __shfl_xor_sync(0xffffffffu, s, 16);
            p += __shfl_xor_sync(0xffffffffu, p, 4);
            p += __shfl_xor_sync(0xffffffffu, p, 8);
            p += __shfl_xor_sync(0xffffffffu, p, 16);
            if ((lane >> 2) == 0) {
                colSsm[wm * 128 + jloc] = s;
                colPsm[wm * 128 + jloc] = p;
            }
        }
    }
    __syncthreads();

    if (tid < 128) {
        g_rowS[(size_t)J * NN + I * 128 + tid] = rowSsm[tid] + rowSsm[128 + tid];
        g_rowP[(size_t)J * NN + I * 128 + tid] = rowPsm[tid] + rowPsm[128 + tid];
        float cs = colSsm[tid] + colSsm[128 + tid] + colSsm[256 + tid] + colSsm[384 + tid];
        float cp = colPsm[tid] + colPsm[128 + tid] + colPsm[256 + tid] + colPsm[384 + tid];
        g_colS[(size_t)I * NN + J * 128 + tid] = cs;
        g_colP[(size_t)I * NN + J * 128 + tid] = cp;
    }
}

// ---------------------------------------------------------------------------
// Kernel 3: deterministic final reduction
// ---------------------------------------------------------------------------
__global__ void finish_kernel(float* __restrict__ out) {
    int i = blockIdx.x * 256 + threadIdx.x;
    if (i >= NN) return;
    float rs = 0.0f, rp = 0.0f, cs = 0.0f, cp = 0.0f;
    #pragma unroll 8
    for (int t = 0; t < NBLK; ++t) {
        rs += g_rowS[(size_t)t * NN + i];
        rp += g_rowP[(size_t)t * NN + i];
        cs += g_colS[(size_t)t * NN + i];
        cp += g_colP[(size_t)t * NN + i];
    }
    float mp = rp / (rs + 1e-8f);
    float sc = cp / (cs + 1e-8f);
    float ans = 0.5f * (-logf(mp + 1e-8f)) + 0.5f * (-logf(sc + 1e-8f));
    if (isnan(ans) || isinf(ans)) ans = 0.0f;
    out[i] = ans;
}

extern "C" void kernel_launch(void* const* d_in, const int* in_sizes, int n_in,
                              void* d_out, int out_size) {
    const float* z_mp = (const float*)d_in[0];
    const float* z_sc = (const float*)d_in[1];
    const float* W1   = (const float*)d_in[2];
    const float* b1   = (const float*)d_in[3];
    const float* W2   = (const float*)d_in[4];
    const float* b2   = (const float*)d_in[5];
    const int*   pos  = (const int*)d_in[6];
    float* out = (float*)d_out;

    cudaFuncSetAttribute(proj_kernel, cudaFuncAttributeMaxDynamicSharedMemorySize,
                         PROJ_SMEM_BYTES);
    cudaFuncSetAttribute(sim_kernel, cudaFuncAttributeMaxDynamicSharedMemorySize,
                         SIM_SMEM_BYTES);

    pack_kernel<<<8192, 256>>>(pos);
    proj_kernel<<<dim3(128, 2), 256, PROJ_SMEM_BYTES>>>(z_mp, z_sc, W1, b1, W2, b2);
    sim_kernel<<<dim3(64, 64), 256, SIM_SMEM_BYTES>>>();
    finish_kernel<<<32, 256>>>(out);
}

// round 5
// speedup vs baseline: 1.7187x; 1.0688x over previous
#include <cuda_runtime.h>
#include <cuda_bf16.h>
#include <cstdint>

#define NN 8192
#define INSZ 256
#define HID 128

// ---------------- device global scratch (allocation-free) ----------------
__device__ __align__(256) __nv_bfloat16 g_Ahi[NN * HID];
__device__ __align__(256) __nv_bfloat16 g_Alo[NN * HID];
__device__ __align__(256) __nv_bfloat16 g_Bhi[NN * HID];
__device__ __align__(256) __nv_bfloat16 g_Blo[NN * HID];
__device__ unsigned g_packed[NN * 256];      // pos bits: [r][c/32]
__device__ float g_rowS[NN * 128];           // [i][Jc]  Jc in 0..127
__device__ float g_rowP[NN * 128];
__device__ float g_colS[NN * 64];            // [j][Ic]  Ic in 0..63
__device__ float g_colP[NN * 64];

// ---------------- helpers ----------------
__device__ __forceinline__ uint32_t smem_u32(const void* p) {
    uint32_t a;
    asm("{ .reg .u64 t; cvta.to.shared.u64 t, %1; cvt.u32.u64 %0, t; }" : "=r"(a) : "l"(p));
    return a;
}
__device__ __forceinline__ float ex2f(float x) {
    float y; asm("ex2.approx.ftz.f32 %0, %1;" : "=f"(y) : "f"(x)); return y;
}
__device__ __forceinline__ void ldsm4(uint32_t a, uint32_t& r0, uint32_t& r1,
                                      uint32_t& r2, uint32_t& r3) {
    asm volatile("ldmatrix.sync.aligned.m8n8.x4.shared.b16 {%0,%1,%2,%3}, [%4];"
                 : "=r"(r0), "=r"(r1), "=r"(r2), "=r"(r3) : "r"(a));
}
__device__ __forceinline__ void mma16816(float* d, const uint32_t* a, const uint32_t* b) {
    asm volatile("mma.sync.aligned.m16n8k16.row.col.f32.bf16.bf16.f32 "
                 "{%0,%1,%2,%3}, {%4,%5,%6,%7}, {%8,%9}, {%0,%1,%2,%3};"
                 : "+f"(d[0]), "+f"(d[1]), "+f"(d[2]), "+f"(d[3])
                 : "r"(a[0]), "r"(a[1]), "r"(a[2]), "r"(a[3]), "r"(b[0]), "r"(b[1]));
}
__device__ __forceinline__ void cp16(uint32_t dst, const void* src) {
    asm volatile("cp.async.cg.shared.global [%0], [%1], 16;" :: "r"(dst), "l"(src));
}
__device__ __forceinline__ void cp_commit_wait() {
    asm volatile("cp.async.commit_group;\n\tcp.async.wait_group 0;" ::: "memory");
}
__device__ __forceinline__ unsigned long long dup2(float a) {
    unsigned long long r; asm("mov.b64 %0, {%1, %1};" : "=l"(r) : "f"(a)); return r;
}
__device__ __forceinline__ void fma2(unsigned long long& d, unsigned long long a,
                                     unsigned long long b) {
    asm("fma.rn.f32x2 %0, %1, %2, %0;" : "+l"(d) : "l"(a), "l"(b));
}
__device__ __forceinline__ float2 unpk(unsigned long long v) {
    float2 r; asm("mov.b64 {%0, %1}, %2;" : "=f"(r.x), "=f"(r.y) : "l"(v)); return r;
}

// ---------------------------------------------------------------------------
// Kernel 1 (fused): blocks [0,256) = projection; blocks [256, 8448) = pos pack.
// proj: Linear->ELU->Linear, L2 norm, bf16 hi/lo split (A pre-scaled 5*log2e).
// pack: DRAM-bound, overlaps with FMA-bound proj.
// ---------------------------------------------------------------------------
#define ZS 68
#define HS 66
#define PROJ_SMEM_FLOATS (64 * ZS + 64 * 128)
#define PROJ_SMEM_BYTES  (PROJ_SMEM_FLOATS * 4)

__global__ void __launch_bounds__(256, 2)
prep_kernel(const float* __restrict__ zA, const float* __restrict__ zB,
            const float* __restrict__ W1, const float* __restrict__ b1,
            const float* __restrict__ W2, const float* __restrict__ b2,
            const int* __restrict__ pos) {
    const int tid = threadIdx.x;

    if (blockIdx.x >= 256) {
        // ---------------- pack path ----------------
        int bid = blockIdx.x - 256;              // 0..8191
        int gw = bid * 8 + (tid >> 5);           // 0..65535
        int lane = tid & 31;
        int br = gw >> 8, bc = gw & 255;
        int r0 = br * 32, c0 = bc * 32;
        int v[32];
        #pragma unroll
        for (int k = 0; k < 32; ++k)
            v[k] = __ldcs(&pos[(size_t)(r0 + k) * NN + c0 + lane]);
        unsigned myw = 0;
        #pragma unroll
        for (int k = 0; k < 32; ++k) {
            unsigned m = __ballot_sync(0xffffffffu, v[k] != 0);
            if (lane == k) myw = m;
        }
        g_packed[(size_t)(r0 + lane) * 256 + bc] = myw;
        return;
    }

    // ---------------- proj path ----------------
    const bool isA = (blockIdx.x < 128);
    const int blk = blockIdx.x & 127;
    const float* z = isA ? zA : zB;
    __nv_bfloat16* hiDst = isA ? g_Ahi : g_Bhi;
    __nv_bfloat16* loDst = isA ? g_Alo : g_Blo;

    extern __shared__ float sm[];
    float* z_s = sm;                 // [64][ZS]
    float* w_s = sm + 64 * ZS;       // [64][128]
    float* h_s = sm;                 // [128][HS] (aliases after phase A)

    const int tx = tid & 15, ty = tid >> 4;
    const int R0 = ty * 4, C0 = tx * 8;
    const float* zblk = z + (size_t)blk * 64 * INSZ;

    unsigned long long acc[4][4];
    #pragma unroll
    for (int i = 0; i < 4; ++i)
        #pragma unroll
        for (int jp = 0; jp < 4; ++jp) acc[i][jp] = 0ull;

    for (int kc = 0; kc < 4; ++kc) {
        __syncthreads();
        #pragma unroll
        for (int it = 0; it < 4; ++it) {
            int e = it * 256 + tid;
            int r = e >> 4, k4 = (e & 15) * 4;
            float4 v = *(const float4*)&zblk[r * INSZ + kc * 64 + k4];
            *(float4*)&z_s[r * ZS + k4] = v;
        }
        #pragma unroll
        for (int it = 0; it < 8; ++it) {
            int e = it * 256 + tid;
            int c4 = (e & 31) * 4, k = e >> 5;
            float4 v = *(const float4*)&W1[(size_t)(kc * 64 + k) * HID + c4];
            *(float4*)&w_s[k * 128 + c4] = v;
        }
        __syncthreads();
        #pragma unroll 4
        for (int k = 0; k < 64; ++k) {
            ulonglong2 bb0 = *(const ulonglong2*)&w_s[k * 128 + C0];
            ulonglong2 bb1 = *(const ulonglong2*)&w_s[k * 128 + C0 + 4];
            #pragma unroll
            for (int i = 0; i < 4; ++i) {
                unsigned long long ad = dup2(z_s[(R0 + i) * ZS + k]);
                fma2(acc[i][0], ad, bb0.x);
                fma2(acc[i][1], ad, bb0.y);
                fma2(acc[i][2], ad, bb1.x);
                fma2(acc[i][3], ad, bb1.y);
            }
        }
    }
    __syncthreads();

    float b1c[8];
    #pragma unroll
    for (int j = 0; j < 8; ++j) b1c[j] = b1[C0 + j];
    #pragma unroll
    for (int i = 0; i < 4; ++i) {
        #pragma unroll
        for (int jp = 0; jp < 4; ++jp) {
            float2 v = unpk(acc[i][jp]);
            float x0 = v.x + b1c[2 * jp];
            float x1 = v.y + b1c[2 * jp + 1];
            x0 = (x0 > 0.0f) ? x0 : (ex2f(fmaxf(x0, -30.0f) * 1.4426950408889634f) - 1.0f);
            x1 = (x1 > 0.0f) ? x1 : (ex2f(fmaxf(x1, -30.0f) * 1.4426950408889634f) - 1.0f);
            h_s[(C0 + 2 * jp)     * HS + R0 + i] = x0;
            h_s[(C0 + 2 * jp + 1) * HS + R0 + i] = x1;
        }
    }
    __syncthreads();

    #pragma unroll
    for (int i = 0; i < 4; ++i)
        #pragma unroll
        for (int jp = 0; jp < 4; ++jp) acc[i][jp] = 0ull;

    #pragma unroll 4
    for (int k = 0; k < 128; ++k) {
        ulonglong2 bb0 = *(const ulonglong2*)&W2[(size_t)k * HID + C0];
        ulonglong2 bb1 = *(const ulonglong2*)&W2[(size_t)k * HID + C0 + 4];
        #pragma unroll
        for (int i = 0; i < 4; ++i) {
            unsigned long long ad = dup2(h_s[k * HS + R0 + i]);
            fma2(acc[i][0], ad, bb0.x);
            fma2(acc[i][1], ad, bb0.y);
            fma2(acc[i][2], ad, bb1.x);
            fma2(acc[i][3], ad, bb1.y);
        }
    }

    float b2c[8];
    #pragma unroll
    for (int j = 0; j < 8; ++j) b2c[j] = b2[C0 + j];

    float x[4][8], ss[4];
    #pragma unroll
    for (int i = 0; i < 4; ++i) {
        float s = 0.0f;
        #pragma unroll
        for (int jp = 0; jp < 4; ++jp) {
            float2 v = unpk(acc[i][jp]);
            float x0 = v.x + b2c[2 * jp];
            float x1 = v.y + b2c[2 * jp + 1];
            x[i][2 * jp] = x0; x[i][2 * jp + 1] = x1;
            s = fmaf(x0, x0, s); s = fmaf(x1, x1, s);
        }
        ss[i] = s;
    }
    #pragma unroll
    for (int m = 1; m < 16; m <<= 1)
        #pragma unroll
        for (int i = 0; i < 4; ++i)
            ss[i] += __shfl_xor_sync(0xffffffffu, ss[i], m);

    const float scl = isA ? 7.2134752044448170f : 1.0f;   // 5 * log2(e) on A
    union { __nv_bfloat16 b[8]; uint4 u; } hv, lv;
    #pragma unroll
    for (int i = 0; i < 4; ++i) {
        float inv = scl / fmaxf(sqrtf(ss[i]), 1e-12f);
        int gRow = blk * 64 + R0 + i;
        #pragma unroll
        for (int j = 0; j < 8; ++j) {
            float v = x[i][j] * inv;
            hv.b[j] = __float2bfloat16(v);
            lv.b[j] = __float2bfloat16(v - __bfloat162float(hv.b[j]));
        }
        *(uint4*)&hiDst[(size_t)gRow * HID + C0] = hv.u;
        *(uint4*)&loDst[(size_t)gRow * HID + C0] = lv.u;
    }
}

// ---------------------------------------------------------------------------
// Kernel 2: fused sim tile 128(M) x 64(N), 2 CTAs/SM. mma.sync bf16 hi/lo split.
// grid = (J=128, I=64), 256 threads = 8 warps (4 M-bands x 2 N-bands).
// ---------------------------------------------------------------------------
#define SM_A0 0
#define SM_A1 32768
#define SM_B0 65536
#define SM_B1 81920
#define SM_POSR 98304
#define SM_POSC 99328
#define SM_ROWS 0
#define SM_ROWP 1024
#define SM_COLS 2048
#define SM_COLP 3072
#define SIM_SMEM_BYTES 100352

__global__ void __launch_bounds__(256, 2) sim_kernel() {
    const int J = blockIdx.x, I = blockIdx.y;
    extern __shared__ char smc[];
    const uint32_t sb = smem_u32(smc);
    const int tid = threadIdx.x;
    const int lane = tid & 31, wid = tid >> 5;
    const int wm = wid & 3, wn = wid >> 2;   // warp tile: rows wm*32..+31, cols wn*32..+31

    // ---- async-load operand tiles (swizzled: chunk c -> c ^ (r&7)) ----
    {
        const uint4* srcA0 = (const uint4*)(g_Ahi + (size_t)I * 128 * HID);
        const uint4* srcA1 = (const uint4*)(g_Alo + (size_t)I * 128 * HID);
        const uint4* srcB0 = (const uint4*)(g_Bhi + (size_t)J * 64 * HID);
        const uint4* srcB1 = (const uint4*)(g_Blo + (size_t)J * 64 * HID);
        #pragma unroll
        for (int it = 0; it < 8; ++it) {
            int e = it * 256 + tid;
            int r = e >> 4, c = e & 15;
            uint32_t so = r * 256 + ((c ^ (r & 7)) << 4);
            cp16(sb + SM_A0 + so, srcA0 + e);
            cp16(sb + SM_A1 + so, srcA1 + e);
            if (it < 4) {
                cp16(sb + SM_B0 + so, srcB0 + e);
                cp16(sb + SM_B1 + so, srcB1 + e);
            }
        }
    }
    // pos bits: row term needs pos[i][j]; col term needs pos[j][i] (both are
    // rows of pos with swapped block indices)
    unsigned* posR = (unsigned*)(smc + SM_POSR);   // [128 rows][2 words]
    unsigned* posC = (unsigned*)(smc + SM_POSC);   // [64 cols][4 words]
    posR[tid] = g_packed[(size_t)(I * 128 + (tid >> 1)) * 256 + J * 2 + (tid & 1)];
    posC[tid] = g_packed[(size_t)(J * 64 + (tid >> 2)) * 256 + I * 4 + (tid & 3)];
    cp_commit_wait();
    __syncthreads();

    // ---- MMA mainloop: 3 split passes (AhiBhi + AhiBlo + AloBhi) ----
    float d[2][4][4];
    #pragma unroll
    for (int mt = 0; mt < 2; ++mt)
        #pragma unroll
        for (int nt = 0; nt < 4; ++nt)
            #pragma unroll
            for (int k = 0; k < 4; ++k) d[mt][nt][k] = 0.0f;

    const int aOff[3] = { SM_A0, SM_A0, SM_A1 };
    const int bOff[3] = { SM_B0, SM_B1, SM_B0 };

    #pragma unroll 1
    for (int s = 0; s < 3; ++s) {
        const uint32_t aB = sb + aOff[s];
        const uint32_t bB = sb + bOff[s];
        #pragma unroll
        for (int ks = 0; ks < 8; ++ks) {
            uint32_t af[2][4];
            #pragma unroll
            for (int mt = 0; mt < 2; ++mt) {
                int row = wm * 32 + mt * 16 + (lane & 15);
                int ch  = ks * 2 + (lane >> 4);
                ldsm4(aB + row * 256 + ((ch ^ (row & 7)) << 4),
                      af[mt][0], af[mt][1], af[mt][2], af[mt][3]);
            }
            uint32_t bf[4][2];
            #pragma unroll
            for (int np = 0; np < 2; ++np) {
                int l = lane & 7, g = lane >> 3;
                int row = wn * 32 + np * 16 + ((g >> 1) << 3) + l;
                int ch  = ks * 2 + (g & 1);
                ldsm4(bB + row * 256 + ((ch ^ (row & 7)) << 4),
                      bf[2 * np][0], bf[2 * np][1], bf[2 * np + 1][0], bf[2 * np + 1][1]);
            }
            #pragma unroll
            for (int mt = 0; mt < 2; ++mt)
                #pragma unroll
                for (int nt = 0; nt < 4; ++nt)
                    mma16816(d[mt][nt], af[mt], bf[nt]);
        }
    }
    __syncthreads();   // operand smem reused for reduction buffers

    // ---- epilogue: exp2, then row/col masked reductions ----
    #pragma unroll
    for (int mt = 0; mt < 2; ++mt)
        #pragma unroll
        for (int nt = 0; nt < 4; ++nt)
            #pragma unroll
            for (int k = 0; k < 4; ++k)
                d[mt][nt][k] = ex2f(d[mt][nt][k]);

    float* rowSsm = (float*)(smc + SM_ROWS);   // [2 wn][128]
    float* rowPsm = (float*)(smc + SM_ROWP);
    float* colSsm = (float*)(smc + SM_COLS);   // [4 wm][64]
    float* colPsm = (float*)(smc + SM_COLP);

    // row sums: thread covers rows (mt, h), its 8 cols (nt x b)
    #pragma unroll
    for (int mt = 0; mt < 2; ++mt) {
        #pragma unroll
        for (int h = 0; h < 2; ++h) {
            int iloc = wm * 32 + mt * 16 + h * 8 + (lane >> 2);
            unsigned w = posR[iloc * 2 + wn];
            float s = 0.0f, p = 0.0f;
            #pragma unroll
            for (int nt = 0; nt < 4; ++nt)
                #pragma unroll
                for (int b = 0; b < 2; ++b) {
                    float e = d[mt][nt][h * 2 + b];
                    s += e;
                    int bit = nt * 8 + (lane & 3) * 2 + b;
                    if ((w >> bit) & 1u) p += e;
                }
            s += __shfl_xor_sync(0xffffffffu, s, 1);
            s += __shfl_xor_sync(0xffffffffu, s, 2);
            p += __shfl_xor_sync(0xffffffffu, p, 1);
            p += __shfl_xor_sync(0xffffffffu, p, 2);
            if ((lane & 3) == 0) {
                rowSsm[wn * 128 + iloc] = s;
                rowPsm[wn * 128 + iloc] = p;
            }
        }
    }

    // col sums: thread covers cols (nt, b), its 4 rows (mt x h)
    #pragma unroll
    for (int nt = 0; nt < 4; ++nt) {
        #pragma unroll
        for (int b = 0; b < 2; ++b) {
            int jloc = wn * 32 + nt * 8 + (lane & 3) * 2 + b;
            unsigned w = posC[jloc * 4 + wm];
            float s = 0.0f, p = 0.0f;
            #pragma unroll
            for (int mt = 0; mt < 2; ++mt)
                #pragma unroll
                for (int h = 0; h < 2; ++h) {
                    float e = d[mt][nt][h * 2 + b];
                    s += e;
                    int bit = mt * 16 + h * 8 + (lane >> 2);
                    if ((w >> bit) & 1u) p += e;
                }
            s += __shfl_xor_sync(0xffffffffu, s, 4);
            s += __shfl_xor_sync(0xffffffffu, s, 8);
            s += __shfl_xor_sync(0xffffffffu, s, 16);
            p += __shfl_xor_sync(0xffffffffu, p, 4);
            p += __shfl_xor_sync(0xffffffffu, p, 8);
            p += __shfl_xor_sync(0xffffffffu, p, 16);
            if ((lane >> 2) == 0) {
                colSsm[wm * 64 + jloc] = s;
                colPsm[wm * 64 + jloc] = p;
            }
        }
    }
    __syncthreads();

    // partial writes in [i][chunk] layout (finish reads become contiguous)
    if (tid < 128) {
        float rs = rowSsm[tid] + rowSsm[128 + tid];
        float rp = rowPsm[tid] + rowPsm[128 + tid];
        g_rowS[(size_t)(I * 128 + tid) * 128 + J] = rs;
        g_rowP[(size_t)(I * 128 + tid) * 128 + J] = rp;
    } else if (tid < 192) {
        int j = tid - 128;
        float cs = colSsm[j] + colSsm[64 + j] + colSsm[128 + j] + colSsm[192 + j];
        float cp = colPsm[j] + colPsm[64 + j] + colPsm[128 + j] + colPsm[192 + j];
        g_colS[(size_t)(J * 64 + j) * 64 + I] = cs;
        g_colP[(size_t)(J * 64 + j) * 64 + I] = cp;
    }
}

// ---------------------------------------------------------------------------
// Kernel 3: deterministic final reduction (contiguous per-thread reads)
// ---------------------------------------------------------------------------
__global__ void finish_kernel(float* __restrict__ out) {
    int i = blockIdx.x * 128 + threadIdx.x;   // grid 64 x 128
    const float4* r4s = (const float4*)&g_rowS[(size_t)i * 128];
    const float4* r4p = (const float4*)&g_rowP[(size_t)i * 128];
    const float4* c4s = (const float4*)&g_colS[(size_t)i * 64];
    const float4* c4p = (const float4*)&g_colP[(size_t)i * 64];
    float rs = 0.0f, rp = 0.0f, cs = 0.0f, cp = 0.0f;
    #pragma unroll 8
    for (int t = 0; t < 32; ++t) {
        float4 a = r4s[t], b = r4p[t];
        rs += (a.x + a.y) + (a.z + a.w);
        rp += (b.x + b.y) + (b.z + b.w);
    }
    #pragma unroll 8
    for (int t = 0; t < 16; ++t) {
        float4 a = c4s[t], b = c4p[t];
        cs += (a.x + a.y) + (a.z + a.w);
        cp += (b.x + b.y) + (b.z + b.w);
    }
    float mp = rp / (rs + 1e-8f);
    float sc = cp / (cs + 1e-8f);
    float ans = 0.5f * (-logf(mp + 1e-8f)) + 0.5f * (-logf(sc + 1e-8f));
    if (isnan(ans) || isinf(ans)) ans = 0.0f;
    out[i] = ans;
}

extern "C" void kernel_launch(void* const* d_in, const int* in_sizes, int n_in,
                              void* d_out, int out_size) {
    const float* z_mp = (const float*)d_in[0];
    const float* z_sc = (const float*)d_in[1];
    const float* W1   = (const float*)d_in[2];
    const float* b1   = (const float*)d_in[3];
    const float* W2   = (const float*)d_in[4];
    const float* b2   = (const float*)d_in[5];
    const int*   pos  = (const int*)d_in[6];
    float* out = (float*)d_out;

    cudaFuncSetAttribute(prep_kernel, cudaFuncAttributeMaxDynamicSharedMemorySize,
                         PROJ_SMEM_BYTES);
    cudaFuncSetAttribute(sim_kernel, cudaFuncAttributeMaxDynamicSharedMemorySize,
                         SIM_SMEM_BYTES);

    prep_kernel<<<8448, 256, PROJ_SMEM_BYTES>>>(z_mp, z_sc, W1, b1, W2, b2, pos);
    sim_kernel<<<dim3(128, 64), 256, SIM_SMEM_BYTES>>>();
    finish_kernel<<<64, 128>>>(out);
}

// round 6
// speedup vs baseline: 2.0182x; 1.1742x over previous
#include <cuda_runtime.h>
#include <cuda_bf16.h>
#include <cstdint>

#define NN 8192
#define INSZ 256
#define HID 128

// ---------------- device global scratch (allocation-free) ----------------
__device__ __align__(256) __nv_bfloat16 g_Ahi[NN * HID];
__device__ __align__(256) __nv_bfloat16 g_Alo[NN * HID];
__device__ __align__(256) __nv_bfloat16 g_Bhi[NN * HID];
__device__ unsigned g_packed[NN * 256];      // pos bits: [r][c/32]
__device__ float g_rowS[NN * 128];           // [i][Jc]  Jc in 0..127
__device__ float g_rowP[NN * 128];
__device__ float g_colS[NN * 64];            // [j][Ic]  Ic in 0..63
__device__ float g_colP[NN * 64];

// ---------------- helpers ----------------
__device__ __forceinline__ uint32_t smem_u32(const void* p) {
    uint32_t a;
    asm("{ .reg .u64 t; cvta.to.shared.u64 t, %1; cvt.u32.u64 %0, t; }" : "=r"(a) : "l"(p));
    return a;
}
__device__ __forceinline__ float ex2f(float x) {
    float y; asm("ex2.approx.ftz.f32 %0, %1;" : "=f"(y) : "f"(x)); return y;
}
__device__ __forceinline__ void ldsm4(uint32_t a, uint32_t& r0, uint32_t& r1,
                                      uint32_t& r2, uint32_t& r3) {
    asm volatile("ldmatrix.sync.aligned.m8n8.x4.shared.b16 {%0,%1,%2,%3}, [%4];"
                 : "=r"(r0), "=r"(r1), "=r"(r2), "=r"(r3) : "r"(a));
}
__device__ __forceinline__ void mma16816(float* d, const uint32_t* a, const uint32_t* b) {
    asm volatile("mma.sync.aligned.m16n8k16.row.col.f32.bf16.bf16.f32 "
                 "{%0,%1,%2,%3}, {%4,%5,%6,%7}, {%8,%9}, {%0,%1,%2,%3};"
                 : "+f"(d[0]), "+f"(d[1]), "+f"(d[2]), "+f"(d[3])
                 : "r"(a[0]), "r"(a[1]), "r"(a[2]), "r"(a[3]), "r"(b[0]), "r"(b[1]));
}
__device__ __forceinline__ void cp16(uint32_t dst, const void* src) {
    asm volatile("cp.async.cg.shared.global [%0], [%1], 16;" :: "r"(dst), "l"(src));
}
__device__ __forceinline__ void cp_commit_wait() {
    asm volatile("cp.async.commit_group;\n\tcp.async.wait_group 0;" ::: "memory");
}
__device__ __forceinline__ unsigned long long dup2(float a) {
    unsigned long long r; asm("mov.b64 %0, {%1, %1};" : "=l"(r) : "f"(a)); return r;
}
__device__ __forceinline__ void fma2(unsigned long long& d, unsigned long long a,
                                     unsigned long long b) {
    asm("fma.rn.f32x2 %0, %1, %2, %0;" : "+l"(d) : "l"(a), "l"(b));
}
__device__ __forceinline__ float2 unpk(unsigned long long v) {
    float2 r; asm("mov.b64 {%0, %1}, %2;" : "=f"(r.x), "=f"(r.y) : "l"(v)); return r;
}

// ---------------------------------------------------------------------------
// Kernel P: pack pos rows into bitmasks. Coalesced int4 reads (4 wavefronts
// per LDG), nibble assembly + 3-step shfl-OR combine within 8-lane groups.
// One warp packs 1024 cols of one row. grid = 8192 x 256 threads.
// ---------------------------------------------------------------------------
__global__ void __launch_bounds__(256) pack_kernel(const int* __restrict__ pos) {
    int gw = blockIdx.x * 8 + (threadIdx.x >> 5);   // warp 0..65535
    int lane = threadIdx.x & 31;
    int r = gw >> 3;
    int chunk = gw & 7;                              // 1024-col chunk
    const int4* base = (const int4*)(pos + (size_t)r * NN + chunk * 1024);
    unsigned wordsBase = (unsigned)r * 256 + chunk * 32;

    int4 v[8];
    #pragma unroll
    for (int t = 0; t < 8; ++t) v[t] = __ldcs(&base[t * 32 + lane]);

    #pragma unroll
    for (int t = 0; t < 8; ++t) {
        unsigned nib = (unsigned)(v[t].x != 0) | ((unsigned)(v[t].y != 0) << 1)
                     | ((unsigned)(v[t].z != 0) << 2) | ((unsigned)(v[t].w != 0) << 3);
        unsigned x = nib << ((lane & 7) * 4);
        x |= __shfl_xor_sync(0xffffffffu, x, 1);
        x |= __shfl_xor_sync(0xffffffffu, x, 2);
        x |= __shfl_xor_sync(0xffffffffu, x, 4);
        if ((lane & 7) == 0)
            g_packed[wordsBase + t * 4 + (lane >> 3)] = x;
    }
}

// ---------------------------------------------------------------------------
// Kernel 1: projection + L2 norm + bf16 split (A = hi+lo, pre-scaled 5*log2e;
// B = hi only — the A*Blo cross term is dropped in the 2-pass sim GEMM).
// grid = (128 row-blocks of 64, 2 inputs), 256 threads.
// ---------------------------------------------------------------------------
#define ZS 68
#define HS 66
#define PROJ_SMEM_FLOATS (64 * ZS + 64 * 128)
#define PROJ_SMEM_BYTES  (PROJ_SMEM_FLOATS * 4)

__global__ void __launch_bounds__(256, 2)
proj_kernel(const float* __restrict__ zA, const float* __restrict__ zB,
            const float* __restrict__ W1, const float* __restrict__ b1,
            const float* __restrict__ W2, const float* __restrict__ b2) {
    const bool isA = (blockIdx.y == 0);
    const float* z = isA ? zA : zB;
    __nv_bfloat16* hiDst = isA ? g_Ahi : g_Bhi;

    extern __shared__ float sm[];
    float* z_s = sm;                 // [64][ZS]
    float* w_s = sm + 64 * ZS;       // [64][128]
    float* h_s = sm;                 // [128][HS] (aliases after phase A)

    const int tid = threadIdx.x;
    const int tx = tid & 15, ty = tid >> 4;
    const int R0 = ty * 4, C0 = tx * 8;
    const int blk = blockIdx.x;
    const float* zblk = z + (size_t)blk * 64 * INSZ;

    unsigned long long acc[4][4];
    #pragma unroll
    for (int i = 0; i < 4; ++i)
        #pragma unroll
        for (int jp = 0; jp < 4; ++jp) acc[i][jp] = 0ull;

    for (int kc = 0; kc < 4; ++kc) {
        __syncthreads();
        #pragma unroll
        for (int it = 0; it < 4; ++it) {
            int e = it * 256 + tid;
            int r = e >> 4, k4 = (e & 15) * 4;
            float4 v = *(const float4*)&zblk[r * INSZ + kc * 64 + k4];
            *(float4*)&z_s[r * ZS + k4] = v;
        }
        #pragma unroll
        for (int it = 0; it < 8; ++it) {
            int e = it * 256 + tid;
            int c4 = (e & 31) * 4, k = e >> 5;
            float4 v = *(const float4*)&W1[(size_t)(kc * 64 + k) * HID + c4];
            *(float4*)&w_s[k * 128 + c4] = v;
        }
        __syncthreads();
        #pragma unroll 4
        for (int k = 0; k < 64; ++k) {
            ulonglong2 bb0 = *(const ulonglong2*)&w_s[k * 128 + C0];
            ulonglong2 bb1 = *(const ulonglong2*)&w_s[k * 128 + C0 + 4];
            #pragma unroll
            for (int i = 0; i < 4; ++i) {
                unsigned long long ad = dup2(z_s[(R0 + i) * ZS + k]);
                fma2(acc[i][0], ad, bb0.x);
                fma2(acc[i][1], ad, bb0.y);
                fma2(acc[i][2], ad, bb1.x);
                fma2(acc[i][3], ad, bb1.y);
            }
        }
    }
    __syncthreads();

    float b1c[8];
    #pragma unroll
    for (int j = 0; j < 8; ++j) b1c[j] = b1[C0 + j];
    #pragma unroll
    for (int i = 0; i < 4; ++i) {
        #pragma unroll
        for (int jp = 0; jp < 4; ++jp) {
            float2 v = unpk(acc[i][jp]);
            float x0 = v.x + b1c[2 * jp];
            float x1 = v.y + b1c[2 * jp + 1];
            x0 = (x0 > 0.0f) ? x0 : (ex2f(fmaxf(x0, -30.0f) * 1.4426950408889634f) - 1.0f);
            x1 = (x1 > 0.0f) ? x1 : (ex2f(fmaxf(x1, -30.0f) * 1.4426950408889634f) - 1.0f);
            h_s[(C0 + 2 * jp)     * HS + R0 + i] = x0;
            h_s[(C0 + 2 * jp + 1) * HS + R0 + i] = x1;
        }
    }
    __syncthreads();

    #pragma unroll
    for (int i = 0; i < 4; ++i)
        #pragma unroll
        for (int jp = 0; jp < 4; ++jp) acc[i][jp] = 0ull;

    #pragma unroll 4
    for (int k = 0; k < 128; ++k) {
        ulonglong2 bb0 = *(const ulonglong2*)&W2[(size_t)k * HID + C0];
        ulonglong2 bb1 = *(const ulonglong2*)&W2[(size_t)k * HID + C0 + 4];
        #pragma unroll
        for (int i = 0; i < 4; ++i) {
            unsigned long long ad = dup2(h_s[k * HS + R0 + i]);
            fma2(acc[i][0], ad, bb0.x);
            fma2(acc[i][1], ad, bb0.y);
            fma2(acc[i][2], ad, bb1.x);
            fma2(acc[i][3], ad, bb1.y);
        }
    }

    float b2c[8];
    #pragma unroll
    for (int j = 0; j < 8; ++j) b2c[j] = b2[C0 + j];

    float x[4][8], ss[4];
    #pragma unroll
    for (int i = 0; i < 4; ++i) {
        float s = 0.0f;
        #pragma unroll
        for (int jp = 0; jp < 4; ++jp) {
            float2 v = unpk(acc[i][jp]);
            float x0 = v.x + b2c[2 * jp];
            float x1 = v.y + b2c[2 * jp + 1];
            x[i][2 * jp] = x0; x[i][2 * jp + 1] = x1;
            s = fmaf(x0, x0, s); s = fmaf(x1, x1, s);
        }
        ss[i] = s;
    }
    #pragma unroll
    for (int m = 1; m < 16; m <<= 1)
        #pragma unroll
        for (int i = 0; i < 4; ++i)
            ss[i] += __shfl_xor_sync(0xffffffffu, ss[i], m);

    const float scl = isA ? 7.2134752044448170f : 1.0f;   // 5 * log2(e) on A
    union { __nv_bfloat16 b[8]; uint4 u; } hv, lv;
    #pragma unroll
    for (int i = 0; i < 4; ++i) {
        float inv = scl / fmaxf(sqrtf(ss[i]), 1e-12f);
        int gRow = blk * 64 + R0 + i;
        #pragma unroll
        for (int j = 0; j < 8; ++j) {
            float v = x[i][j] * inv;
            hv.b[j] = __float2bfloat16(v);
            lv.b[j] = __float2bfloat16(v - __bfloat162float(hv.b[j]));
        }
        *(uint4*)&hiDst[(size_t)gRow * HID + C0] = hv.u;
        if (isA)
            *(uint4*)&g_Alo[(size_t)gRow * HID + C0] = lv.u;
    }
}

// ---------------------------------------------------------------------------
// Kernel 2: fused sim tile 128(M) x 64(N), 2 CTAs/SM. 2-pass bf16 split:
// D = Ahi*Bhi + Alo*Bhi (fp32 accum); B fragments reused across passes.
// grid = (J=128, I=64), 256 threads = 8 warps (4 M-bands x 2 N-bands).
// ---------------------------------------------------------------------------
#define SM_A0 0
#define SM_A1 32768
#define SM_B0 65536
#define SM_POSR 81920
#define SM_POSC 82944
#define SM_ROWS 0
#define SM_ROWP 1024
#define SM_COLS 2048
#define SM_COLP 3072
#define SIM_SMEM_BYTES 83968

__global__ void __launch_bounds__(256, 2) sim_kernel() {
    const int J = blockIdx.x, I = blockIdx.y;
    extern __shared__ char smc[];
    const uint32_t sb = smem_u32(smc);
    const int tid = threadIdx.x;
    const int lane = tid & 31, wid = tid >> 5;
    const int wm = wid & 3, wn = wid >> 2;   // warp tile: rows wm*32..+31, cols wn*32..+31

    // ---- async-load operand tiles (swizzled: chunk c -> c ^ (r&7)) ----
    {
        const uint4* srcA0 = (const uint4*)(g_Ahi + (size_t)I * 128 * HID);
        const uint4* srcA1 = (const uint4*)(g_Alo + (size_t)I * 128 * HID);
        const uint4* srcB0 = (const uint4*)(g_Bhi + (size_t)J * 64 * HID);
        #pragma unroll
        for (int it = 0; it < 8; ++it) {
            int e = it * 256 + tid;
            int r = e >> 4, c = e & 15;
            uint32_t so = r * 256 + ((c ^ (r & 7)) << 4);
            cp16(sb + SM_A0 + so, srcA0 + e);
            cp16(sb + SM_A1 + so, srcA1 + e);
            if (it < 4) cp16(sb + SM_B0 + so, srcB0 + e);
        }
    }
    // pos bits: row term needs pos[i][j]; col term needs pos[j][i] (both are
    // rows of pos with swapped block indices)
    unsigned* posR = (unsigned*)(smc + SM_POSR);   // [128 rows][2 words]
    unsigned* posC = (unsigned*)(smc + SM_POSC);   // [64 cols][4 words]
    posR[tid] = g_packed[(size_t)(I * 128 + (tid >> 1)) * 256 + J * 2 + (tid & 1)];
    posC[tid] = g_packed[(size_t)(J * 64 + (tid >> 2)) * 256 + I * 4 + (tid & 3)];
    cp_commit_wait();
    __syncthreads();

    // ---- MMA mainloop: per k-step, load B once, run Ahi and Alo passes ----
    float d[2][4][4];
    #pragma unroll
    for (int mt = 0; mt < 2; ++mt)
        #pragma unroll
        for (int nt = 0; nt < 4; ++nt)
            #pragma unroll
            for (int k = 0; k < 4; ++k) d[mt][nt][k] = 0.0f;

    const uint32_t aB0 = sb + SM_A0, aB1 = sb + SM_A1, bB = sb + SM_B0;

    #pragma unroll
    for (int ks = 0; ks < 8; ++ks) {
        uint32_t bf[4][2];
        #pragma unroll
        for (int np = 0; np < 2; ++np) {
            int l = lane & 7, g = lane >> 3;
            int row = wn * 32 + np * 16 + ((g >> 1) << 3) + l;
            int ch  = ks * 2 + (g & 1);
            ldsm4(bB + row * 256 + ((ch ^ (row & 7)) << 4),
                  bf[2 * np][0], bf[2 * np][1], bf[2 * np + 1][0], bf[2 * np + 1][1]);
        }
        uint32_t af0[2][4], af1[2][4];
        #pragma unroll
        for (int mt = 0; mt < 2; ++mt) {
            int row = wm * 32 + mt * 16 + (lane & 15);
            int ch  = ks * 2 + (lane >> 4);
            uint32_t so = row * 256 + ((ch ^ (row & 7)) << 4);
            ldsm4(aB0 + so, af0[mt][0], af0[mt][1], af0[mt][2], af0[mt][3]);
            ldsm4(aB1 + so, af1[mt][0], af1[mt][1], af1[mt][2], af1[mt][3]);
        }
        #pragma unroll
        for (int mt = 0; mt < 2; ++mt)
            #pragma unroll
            for (int nt = 0; nt < 4; ++nt)
                mma16816(d[mt][nt], af0[mt], bf[nt]);
        #pragma unroll
        for (int mt = 0; mt < 2; ++mt)
            #pragma unroll
            for (int nt = 0; nt < 4; ++nt)
                mma16816(d[mt][nt], af1[mt], bf[nt]);
    }
    __syncthreads();   // operand smem reused for reduction buffers

    // ---- epilogue: exp2, then row/col masked reductions ----
    #pragma unroll
    for (int mt = 0; mt < 2; ++mt)
        #pragma unroll
        for (int nt = 0; nt < 4; ++nt)
            #pragma unroll
            for (int k = 0; k < 4; ++k)
                d[mt][nt][k] = ex2f(d[mt][nt][k]);

    float* rowSsm = (float*)(smc + SM_ROWS);   // [2 wn][128]
    float* rowPsm = (float*)(smc + SM_ROWP);
    float* colSsm = (float*)(smc + SM_COLS);   // [4 wm][64]
    float* colPsm = (float*)(smc + SM_COLP);

    // row sums: thread covers rows (mt, h), its 8 cols (nt x b)
    #pragma unroll
    for (int mt = 0; mt < 2; ++mt) {
        #pragma unroll
        for (int h = 0; h < 2; ++h) {
            int iloc = wm * 32 + mt * 16 + h * 8 + (lane >> 2);
            unsigned w = posR[iloc * 2 + wn];
            float s = 0.0f, p = 0.0f;
            #pragma unroll
            for (int nt = 0; nt < 4; ++nt)
                #pragma unroll
                for (int b = 0; b < 2; ++b) {
                    float e = d[mt][nt][h * 2 + b];
                    s += e;
                    int bit = nt * 8 + (lane & 3) * 2 + b;
                    if ((w >> bit) & 1u) p += e;
                }
            s += __shfl_xor_sync(0xffffffffu, s, 1);
            s += __shfl_xor_sync(0xffffffffu, s, 2);
            p += __shfl_xor_sync(0xffffffffu, p, 1);
            p += __shfl_xor_sync(0xffffffffu, p, 2);
            if ((lane & 3) == 0) {
                rowSsm[wn * 128 + iloc] = s;
                rowPsm[wn * 128 + iloc] = p;
            }
        }
    }

    // col sums: thread covers cols (nt, b), its 4 rows (mt x h)
    #pragma unroll
    for (int nt = 0; nt < 4; ++nt) {
        #pragma unroll
        for (int b = 0; b < 2; ++b) {
            int jloc = wn * 32 + nt * 8 + (lane & 3) * 2 + b;
            unsigned w = posC[jloc * 4 + wm];
            float s = 0.0f, p = 0.0f;
            #pragma unroll
            for (int mt = 0; mt < 2; ++mt)
                #pragma unroll
                for (int h = 0; h < 2; ++h) {
                    float e = d[mt][nt][h * 2 + b];
                    s += e;
                    int bit = mt * 16 + h * 8 + (lane >> 2);
                    if ((w >> bit) & 1u) p += e;
                }
            s += __shfl_xor_sync(0xffffffffu, s, 4);
            s += __shfl_xor_sync(0xffffffffu, s, 8);
            s += __shfl_xor_sync(0xffffffffu, s, 16);
            p += __shfl_xor_sync(0xffffffffu, p, 4);
            p += __shfl_xor_sync(0xffffffffu, p, 8);
            p += __shfl_xor_sync(0xffffffffu, p, 16);
            if ((lane >> 2) == 0) {
                colSsm[wm * 64 + jloc] = s;
                colPsm[wm * 64 + jloc] = p;
            }
        }
    }
    __syncthreads();

    // partial writes in [i][chunk] layout (finish reads become contiguous)
    if (tid < 128) {
        float rs = rowSsm[tid] + rowSsm[128 + tid];
        float rp = rowPsm[tid] + rowPsm[128 + tid];
        g_rowS[(size_t)(I * 128 + tid) * 128 + J] = rs;
        g_rowP[(size_t)(I * 128 + tid) * 128 + J] = rp;
    } else if (tid < 192) {
        int j = tid - 128;
        float cs = colSsm[j] + colSsm[64 + j] + colSsm[128 + j] + colSsm[192 + j];
        float cp = colPsm[j] + colPsm[64 + j] + colPsm[128 + j] + colPsm[192 + j];
        g_colS[(size_t)(J * 64 + j) * 64 + I] = cs;
        g_colP[(size_t)(J * 64 + j) * 64 + I] = cp;
    }
}

// ---------------------------------------------------------------------------
// Kernel 3: deterministic final reduction (contiguous per-thread reads)
// ---------------------------------------------------------------------------
__global__ void finish_kernel(float* __restrict__ out) {
    int i = blockIdx.x * 128 + threadIdx.x;   // grid 64 x 128
    const float4* r4s = (const float4*)&g_rowS[(size_t)i * 128];
    const float4* r4p = (const float4*)&g_rowP[(size_t)i * 128];
    const float4* c4s = (const float4*)&g_colS[(size_t)i * 64];
    const float4* c4p = (const float4*)&g_colP[(size_t)i * 64];
    float rs = 0.0f, rp = 0.0f, cs = 0.0f, cp = 0.0f;
    #pragma unroll 8
    for (int t = 0; t < 32; ++t) {
        float4 a = r4s[t], b = r4p[t];
        rs += (a.x + a.y) + (a.z + a.w);
        rp += (b.x + b.y) + (b.z + b.w);
    }
    #pragma unroll 8
    for (int t = 0; t < 16; ++t) {
        float4 a = c4s[t], b = c4p[t];
        cs += (a.x + a.y) + (a.z + a.w);
        cp += (b.x + b.y) + (b.z + b.w);
    }
    float mp = rp / (rs + 1e-8f);
    float sc = cp / (cs + 1e-8f);
    float ans = 0.5f * (-logf(mp + 1e-8f)) + 0.5f * (-logf(sc + 1e-8f));
    if (isnan(ans) || isinf(ans)) ans = 0.0f;
    out[i] = ans;
}

extern "C" void kernel_launch(void* const* d_in, const int* in_sizes, int n_in,
                              void* d_out, int out_size) {
    const float* z_mp = (const float*)d_in[0];
    const float* z_sc = (const float*)d_in[1];
    const float* W1   = (const float*)d_in[2];
    const float* b1   = (const float*)d_in[3];
    const float* W2   = (const float*)d_in[4];
    const float* b2   = (const float*)d_in[5];
    const int*   pos  = (const int*)d_in[6];
    float* out = (float*)d_out;

    cudaFuncSetAttribute(proj_kernel, cudaFuncAttributeMaxDynamicSharedMemorySize,
                         PROJ_SMEM_BYTES);
    cudaFuncSetAttribute(sim_kernel, cudaFuncAttributeMaxDynamicSharedMemorySize,
                         SIM_SMEM_BYTES);

    pack_kernel<<<8192, 256>>>(pos);
    proj_kernel<<<dim3(128, 2), 256, PROJ_SMEM_BYTES>>>(z_mp, z_sc, W1, b1, W2, b2);
    sim_kernel<<<dim3(128, 64), 256, SIM_SMEM_BYTES>>>();
    finish_kernel<<<64, 128>>>(out);
}

// round 7
// speedup vs baseline: 2.4546x; 1.2163x over previous
#include <cuda_runtime.h>
#include <cuda_bf16.h>
#include <cstdint>

#define NN 8192
#define INSZ 256
#define HID 128

// ---------------- device global scratch (allocation-free) ----------------
__device__ __align__(256) __nv_bfloat16 g_Ahi[NN * HID];
__device__ __align__(256) __nv_bfloat16 g_Bhi[NN * HID];
__device__ unsigned g_packed[NN * 256];      // pos bits: [r][c/32]
__device__ float g_rowS[NN * 128];           // [i][Jc]  Jc in 0..127
__device__ float g_rowP[NN * 128];
__device__ float g_colS[NN * 64];            // [j][Ic]  Ic in 0..63
__device__ float g_colP[NN * 64];

// ---------------- helpers ----------------
__device__ __forceinline__ uint32_t smem_u32(const void* p) {
    uint32_t a;
    asm("{ .reg .u64 t; cvta.to.shared.u64 t, %1; cvt.u32.u64 %0, t; }" : "=r"(a) : "l"(p));
    return a;
}
__device__ __forceinline__ float ex2f(float x) {
    float y; asm("ex2.approx.ftz.f32 %0, %1;" : "=f"(y) : "f"(x)); return y;
}
__device__ __forceinline__ void ldsm4(uint32_t a, uint32_t& r0, uint32_t& r1,
                                      uint32_t& r2, uint32_t& r3) {
    asm volatile("ldmatrix.sync.aligned.m8n8.x4.shared.b16 {%0,%1,%2,%3}, [%4];"
                 : "=r"(r0), "=r"(r1), "=r"(r2), "=r"(r3) : "r"(a));
}
__device__ __forceinline__ void mma16816(float* d, const uint32_t* a, const uint32_t* b) {
    asm volatile("mma.sync.aligned.m16n8k16.row.col.f32.bf16.bf16.f32 "
                 "{%0,%1,%2,%3}, {%4,%5,%6,%7}, {%8,%9}, {%0,%1,%2,%3};"
                 : "+f"(d[0]), "+f"(d[1]), "+f"(d[2]), "+f"(d[3])
                 : "r"(a[0]), "r"(a[1]), "r"(a[2]), "r"(a[3]), "r"(b[0]), "r"(b[1]));
}
__device__ __forceinline__ void cp16(uint32_t dst, const void* src) {
    asm volatile("cp.async.cg.shared.global [%0], [%1], 16;" :: "r"(dst), "l"(src));
}
__device__ __forceinline__ void cp_commit_wait() {
    asm volatile("cp.async.commit_group;\n\tcp.async.wait_group 0;" ::: "memory");
}
__device__ __forceinline__ unsigned long long dup2(float a) {
    unsigned long long r; asm("mov.b64 %0, {%1, %1};" : "=l"(r) : "f"(a)); return r;
}
__device__ __forceinline__ void fma2(unsigned long long& d, unsigned long long a,
                                     unsigned long long b) {
    asm("fma.rn.f32x2 %0, %1, %2, %0;" : "+l"(d) : "l"(a), "l"(b));
}
__device__ __forceinline__ float2 unpk(unsigned long long v) {
    float2 r; asm("mov.b64 {%0, %1}, %2;" : "=f"(r.x), "=f"(r.y) : "l"(v)); return r;
}

// ---------------------------------------------------------------------------
// Kernel P: pack pos rows into bitmasks. Coalesced int4 reads, nibble
// assembly + shfl-OR combine. One warp packs 1024 cols of one row.
// ---------------------------------------------------------------------------
__global__ void __launch_bounds__(256) pack_kernel(const int* __restrict__ pos) {
    int gw = blockIdx.x * 8 + (threadIdx.x >> 5);   // warp 0..65535
    int lane = threadIdx.x & 31;
    int r = gw >> 3;
    int chunk = gw & 7;                              // 1024-col chunk
    const int4* base = (const int4*)(pos + (size_t)r * NN + chunk * 1024);
    unsigned wordsBase = (unsigned)r * 256 + chunk * 32;

    int4 v[8];
    #pragma unroll
    for (int t = 0; t < 8; ++t) v[t] = __ldcs(&base[t * 32 + lane]);

    #pragma unroll
    for (int t = 0; t < 8; ++t) {
        unsigned nib = (unsigned)(v[t].x != 0) | ((unsigned)(v[t].y != 0) << 1)
                     | ((unsigned)(v[t].z != 0) << 2) | ((unsigned)(v[t].w != 0) << 3);
        unsigned x = nib << ((lane & 7) * 4);
        x |= __shfl_xor_sync(0xffffffffu, x, 1);
        x |= __shfl_xor_sync(0xffffffffu, x, 2);
        x |= __shfl_xor_sync(0xffffffffu, x, 4);
        if ((lane & 7) == 0)
            g_packed[wordsBase + t * 4 + (lane >> 3)] = x;
    }
}

// ---------------------------------------------------------------------------
// Kernel 1: projection + L2 norm -> single bf16 output (A pre-scaled 5*log2e).
// grid = (128 row-blocks of 64, 2 inputs), 256 threads.
// ---------------------------------------------------------------------------
#define ZS 68
#define HS 66
#define PROJ_SMEM_FLOATS (64 * ZS + 64 * 128)
#define PROJ_SMEM_BYTES  (PROJ_SMEM_FLOATS * 4)

__global__ void __launch_bounds__(256, 2)
proj_kernel(const float* __restrict__ zA, const float* __restrict__ zB,
            const float* __restrict__ W1, const float* __restrict__ b1,
            const float* __restrict__ W2, const float* __restrict__ b2) {
    const bool isA = (blockIdx.y == 0);
    const float* z = isA ? zA : zB;
    __nv_bfloat16* hiDst = isA ? g_Ahi : g_Bhi;

    extern __shared__ float sm[];
    float* z_s = sm;                 // [64][ZS]
    float* w_s = sm + 64 * ZS;       // [64][128]
    float* h_s = sm;                 // [128][HS] (aliases after phase A)

    const int tid = threadIdx.x;
    const int tx = tid & 15, ty = tid >> 4;
    const int R0 = ty * 4, C0 = tx * 8;
    const int blk = blockIdx.x;
    const float* zblk = z + (size_t)blk * 64 * INSZ;

    unsigned long long acc[4][4];
    #pragma unroll
    for (int i = 0; i < 4; ++i)
        #pragma unroll
        for (int jp = 0; jp < 4; ++jp) acc[i][jp] = 0ull;

    for (int kc = 0; kc < 4; ++kc) {
        __syncthreads();
        #pragma unroll
        for (int it = 0; it < 4; ++it) {
            int e = it * 256 + tid;
            int r = e >> 4, k4 = (e & 15) * 4;
            float4 v = *(const float4*)&zblk[r * INSZ + kc * 64 + k4];
            *(float4*)&z_s[r * ZS + k4] = v;
        }
        #pragma unroll
        for (int it = 0; it < 8; ++it) {
            int e = it * 256 + tid;
            int c4 = (e & 31) * 4, k = e >> 5;
            float4 v = *(const float4*)&W1[(size_t)(kc * 64 + k) * HID + c4];
            *(float4*)&w_s[k * 128 + c4] = v;
        }
        __syncthreads();
        #pragma unroll 4
        for (int k = 0; k < 64; ++k) {
            ulonglong2 bb0 = *(const ulonglong2*)&w_s[k * 128 + C0];
            ulonglong2 bb1 = *(const ulonglong2*)&w_s[k * 128 + C0 + 4];
            #pragma unroll
            for (int i = 0; i < 4; ++i) {
                unsigned long long ad = dup2(z_s[(R0 + i) * ZS + k]);
                fma2(acc[i][0], ad, bb0.x);
                fma2(acc[i][1], ad, bb0.y);
                fma2(acc[i][2], ad, bb1.x);
                fma2(acc[i][3], ad, bb1.y);
            }
        }
    }
    __syncthreads();

    float b1c[8];
    #pragma unroll
    for (int j = 0; j < 8; ++j) b1c[j] = b1[C0 + j];
    #pragma unroll
    for (int i = 0; i < 4; ++i) {
        #pragma unroll
        for (int jp = 0; jp < 4; ++jp) {
            float2 v = unpk(acc[i][jp]);
            float x0 = v.x + b1c[2 * jp];
            float x1 = v.y + b1c[2 * jp + 1];
            x0 = (x0 > 0.0f) ? x0 : (ex2f(fmaxf(x0, -30.0f) * 1.4426950408889634f) - 1.0f);
            x1 = (x1 > 0.0f) ? x1 : (ex2f(fmaxf(x1, -30.0f) * 1.4426950408889634f) - 1.0f);
            h_s[(C0 + 2 * jp)     * HS + R0 + i] = x0;
            h_s[(C0 + 2 * jp + 1) * HS + R0 + i] = x1;
        }
    }
    __syncthreads();

    #pragma unroll
    for (int i = 0; i < 4; ++i)
        #pragma unroll
        for (int jp = 0; jp < 4; ++jp) acc[i][jp] = 0ull;

    #pragma unroll 4
    for (int k = 0; k < 128; ++k) {
        ulonglong2 bb0 = *(const ulonglong2*)&W2[(size_t)k * HID + C0];
        ulonglong2 bb1 = *(const ulonglong2*)&W2[(size_t)k * HID + C0 + 4];
        #pragma unroll
        for (int i = 0; i < 4; ++i) {
            unsigned long long ad = dup2(h_s[k * HS + R0 + i]);
            fma2(acc[i][0], ad, bb0.x);
            fma2(acc[i][1], ad, bb0.y);
            fma2(acc[i][2], ad, bb1.x);
            fma2(acc[i][3], ad, bb1.y);
        }
    }

    float b2c[8];
    #pragma unroll
    for (int j = 0; j < 8; ++j) b2c[j] = b2[C0 + j];

    float x[4][8], ss[4];
    #pragma unroll
    for (int i = 0; i < 4; ++i) {
        float s = 0.0f;
        #pragma unroll
        for (int jp = 0; jp < 4; ++jp) {
            float2 v = unpk(acc[i][jp]);
            float x0 = v.x + b2c[2 * jp];
            float x1 = v.y + b2c[2 * jp + 1];
            x[i][2 * jp] = x0; x[i][2 * jp + 1] = x1;
            s = fmaf(x0, x0, s); s = fmaf(x1, x1, s);
        }
        ss[i] = s;
    }
    #pragma unroll
    for (int m = 1; m < 16; m <<= 1)
        #pragma unroll
        for (int i = 0; i < 4; ++i)
            ss[i] += __shfl_xor_sync(0xffffffffu, ss[i], m);

    const float scl = isA ? 7.2134752044448170f : 1.0f;   // 5 * log2(e) on A
    union { __nv_bfloat16 b[8]; uint4 u; } hv;
    #pragma unroll
    for (int i = 0; i < 4; ++i) {
        float inv = scl / fmaxf(sqrtf(ss[i]), 1e-12f);
        int gRow = blk * 64 + R0 + i;
        #pragma unroll
        for (int j = 0; j < 8; ++j)
            hv.b[j] = __float2bfloat16(x[i][j] * inv);
        *(uint4*)&hiDst[(size_t)gRow * HID + C0] = hv.u;
    }
}

// ---------------------------------------------------------------------------
// Kernel 2: fused sim tile 128(M) x 64(N), single bf16 pass, 3 CTAs/SM.
// grid = (J=128, I=64), 256 threads = 8 warps (4 M-bands x 2 N-bands).
// ---------------------------------------------------------------------------
#define SM_A0 0
#define SM_B0 32768
#define SM_POSR 49152
#define SM_POSC 50176
#define SM_ROWS 0
#define SM_ROWP 1024
#define SM_COLS 2048
#define SM_COLP 3072
#define SIM_SMEM_BYTES 51200

__global__ void __launch_bounds__(256, 3) sim_kernel() {
    const int J = blockIdx.x, I = blockIdx.y;
    extern __shared__ char smc[];
    const uint32_t sb = smem_u32(smc);
    const int tid = threadIdx.x;
    const int lane = tid & 31, wid = tid >> 5;
    const int wm = wid & 3, wn = wid >> 2;   // warp tile: rows wm*32..+31, cols wn*32..+31

    // ---- async-load operand tiles (swizzled: chunk c -> c ^ (r&7)) ----
    {
        const uint4* srcA0 = (const uint4*)(g_Ahi + (size_t)I * 128 * HID);
        const uint4* srcB0 = (const uint4*)(g_Bhi + (size_t)J * 64 * HID);
        #pragma unroll
        for (int it = 0; it < 8; ++it) {
            int e = it * 256 + tid;
            int r = e >> 4, c = e & 15;
            uint32_t so = r * 256 + ((c ^ (r & 7)) << 4);
            cp16(sb + SM_A0 + so, srcA0 + e);
            if (it < 4) cp16(sb + SM_B0 + so, srcB0 + e);
        }
    }
    // pos bits: row term needs pos[i][j]; col term needs pos[j][i] (both are
    // rows of pos with swapped block indices)
    unsigned* posR = (unsigned*)(smc + SM_POSR);   // [128 rows][2 words]
    unsigned* posC = (unsigned*)(smc + SM_POSC);   // [64 cols][4 words]
    posR[tid] = g_packed[(size_t)(I * 128 + (tid >> 1)) * 256 + J * 2 + (tid & 1)];
    posC[tid] = g_packed[(size_t)(J * 64 + (tid >> 2)) * 256 + I * 4 + (tid & 3)];
    cp_commit_wait();
    __syncthreads();

    // ---- MMA mainloop (single pass) ----
    float d[2][4][4];
    #pragma unroll
    for (int mt = 0; mt < 2; ++mt)
        #pragma unroll
        for (int nt = 0; nt < 4; ++nt)
            #pragma unroll
            for (int k = 0; k < 4; ++k) d[mt][nt][k] = 0.0f;

    const uint32_t aB0 = sb + SM_A0, bB = sb + SM_B0;

    #pragma unroll
    for (int ks = 0; ks < 8; ++ks) {
        uint32_t bf[4][2];
        #pragma unroll
        for (int np = 0; np < 2; ++np) {
            int l = lane & 7, g = lane >> 3;
            int row = wn * 32 + np * 16 + ((g >> 1) << 3) + l;
            int ch  = ks * 2 + (g & 1);
            ldsm4(bB + row * 256 + ((ch ^ (row & 7)) << 4),
                  bf[2 * np][0], bf[2 * np][1], bf[2 * np + 1][0], bf[2 * np + 1][1]);
        }
        uint32_t af0[2][4];
        #pragma unroll
        for (int mt = 0; mt < 2; ++mt) {
            int row = wm * 32 + mt * 16 + (lane & 15);
            int ch  = ks * 2 + (lane >> 4);
            uint32_t so = row * 256 + ((ch ^ (row & 7)) << 4);
            ldsm4(aB0 + so, af0[mt][0], af0[mt][1], af0[mt][2], af0[mt][3]);
        }
        #pragma unroll
        for (int mt = 0; mt < 2; ++mt)
            #pragma unroll
            for (int nt = 0; nt < 4; ++nt)
                mma16816(d[mt][nt], af0[mt], bf[nt]);
    }
    __syncthreads();   // operand smem reused for reduction buffers

    // ---- epilogue: exp2, then row/col masked reductions ----
    #pragma unroll
    for (int mt = 0; mt < 2; ++mt)
        #pragma unroll
        for (int nt = 0; nt < 4; ++nt)
            #pragma unroll
            for (int k = 0; k < 4; ++k)
                d[mt][nt][k] = ex2f(d[mt][nt][k]);

    float* rowSsm = (float*)(smc + SM_ROWS);   // [2 wn][128]
    float* rowPsm = (float*)(smc + SM_ROWP);
    float* colSsm = (float*)(smc + SM_COLS);   // [4 wm][64]
    float* colPsm = (float*)(smc + SM_COLP);

    // row sums: thread covers rows (mt, h), its 8 cols (nt x b)
    #pragma unroll
    for (int mt = 0; mt < 2; ++mt) {
        #pragma unroll
        for (int h = 0; h < 2; ++h) {
            int iloc = wm * 32 + mt * 16 + h * 8 + (lane >> 2);
            unsigned w = posR[iloc * 2 + wn];
            float s = 0.0f, p = 0.0f;
            #pragma unroll
            for (int nt = 0; nt < 4; ++nt)
                #pragma unroll
                for (int b = 0; b < 2; ++b) {
                    float e = d[mt][nt][h * 2 + b];
                    s += e;
                    int bit = nt * 8 + (lane & 3) * 2 + b;
                    if ((w >> bit) & 1u) p += e;
                }
            s += __shfl_xor_sync(0xffffffffu, s, 1);
            s += __shfl_xor_sync(0xffffffffu, s, 2);
            p += __shfl_xor_sync(0xffffffffu, p, 1);
            p += __shfl_xor_sync(0xffffffffu, p, 2);
            if ((lane & 3) == 0) {
                rowSsm[wn * 128 + iloc] = s;
                rowPsm[wn * 128 + iloc] = p;
            }
        }
    }

    // col sums: thread covers cols (nt, b), its 4 rows (mt x h)
    #pragma unroll
    for (int nt = 0; nt < 4; ++nt) {
        #pragma unroll
        for (int b = 0; b < 2; ++b) {
            int jloc = wn * 32 + nt * 8 + (lane & 3) * 2 + b;
            unsigned w = posC[jloc * 4 + wm];
            float s = 0.0f, p = 0.0f;
            #pragma unroll
            for (int mt = 0; mt < 2; ++mt)
                #pragma unroll
                for (int h = 0; h < 2; ++h) {
                    float e = d[mt][nt][h * 2 + b];
                    s += e;
                    int bit = mt * 16 + h * 8 + (lane >> 2);
                    if ((w >> bit) & 1u) p += e;
                }
            s += __shfl_xor_sync(0xffffffffu, s, 4);
            s += __shfl_xor_sync(0xffffffffu, s, 8);
            s += __shfl_xor_sync(0xffffffffu, s, 16);
            p += __shfl_xor_sync(0xffffffffu, p, 4);
            p += __shfl_xor_sync(0xffffffffu, p, 8);
            p += __shfl_xor_sync(0xffffffffu, p, 16);
            if ((lane >> 2) == 0) {
                colSsm[wm * 64 + jloc] = s;
                colPsm[wm * 64 + jloc] = p;
            }
        }
    }
    __syncthreads();

    // partial writes in [i][chunk] layout (finish reads become contiguous)
    if (tid < 128) {
        float rs = rowSsm[tid] + rowSsm[128 + tid];
        float rp = rowPsm[tid] + rowPsm[128 + tid];
        g_rowS[(size_t)(I * 128 + tid) * 128 + J] = rs;
        g_rowP[(size_t)(I * 128 + tid) * 128 + J] = rp;
    } else if (tid < 192) {
        int j = tid - 128;
        float cs = colSsm[j] + colSsm[64 + j] + colSsm[128 + j] + colSsm[192 + j];
        float cp = colPsm[j] + colPsm[64 + j] + colPsm[128 + j] + colPsm[192 + j];
        g_colS[(size_t)(J * 64 + j) * 64 + I] = cs;
        g_colP[(size_t)(J * 64 + j) * 64 + I] = cp;
    }
}

// ---------------------------------------------------------------------------
// Kernel 3: final reduction, 4 threads per row (deterministic, fixed split)
// ---------------------------------------------------------------------------
__global__ void __launch_bounds__(256) finish_kernel(float* __restrict__ out) {
    int g = blockIdx.x * 256 + threadIdx.x;   // grid 128 x 256 = 32768
    int i = g >> 2, q = g & 3;
    const float4* r4s = (const float4*)&g_rowS[(size_t)i * 128];
    const float4* r4p = (const float4*)&g_rowP[(size_t)i * 128];
    const float4* c4s = (const float4*)&g_colS[(size_t)i * 64];
    const float4* c4p = (const float4*)&g_colP[(size_t)i * 64];
    float rs = 0.0f, rp = 0.0f, cs = 0.0f, cp = 0.0f;
    #pragma unroll
    for (int t = 0; t < 8; ++t) {
        float4 a = r4s[q * 8 + t], b = r4p[q * 8 + t];
        rs += (a.x + a.y) + (a.z + a.w);
        rp += (b.x + b.y) + (b.z + b.w);
    }
    #pragma unroll
    for (int t = 0; t < 4; ++t) {
        float4 a = c4s[q * 4 + t], b = c4p[q * 4 + t];
        cs += (a.x + a.y) + (a.z + a.w);
        cp += (b.x + b.y) + (b.z + b.w);
    }
    #pragma unroll
    for (int m = 1; m < 4; m <<= 1) {
        rs += __shfl_xor_sync(0xffffffffu, rs, m);
        rp += __shfl_xor_sync(0xffffffffu, rp, m);
        cs += __shfl_xor_sync(0xffffffffu, cs, m);
        cp += __shfl_xor_sync(0xffffffffu, cp, m);
    }
    if (q == 0) {
        float mp = rp / (rs + 1e-8f);
        float sc = cp / (cs + 1e-8f);
        float ans = 0.5f * (-logf(mp + 1e-8f)) + 0.5f * (-logf(sc + 1e-8f));
        if (isnan(ans) || isinf(ans)) ans = 0.0f;
        out[i] = ans;
    }
}

extern "C" void kernel_launch(void* const* d_in, const int* in_sizes, int n_in,
                              void* d_out, int out_size) {
    const float* z_mp = (const float*)d_in[0];
    const float* z_sc = (const float*)d_in[1];
    const float* W1   = (const float*)d_in[2];
    const float* b1   = (const float*)d_in[3];
    const float* W2   = (const float*)d_in[4];
    const float* b2   = (const float*)d_in[5];
    const int*   pos  = (const int*)d_in[6];
    float* out = (float*)d_out;

    cudaFuncSetAttribute(proj_kernel, cudaFuncAttributeMaxDynamicSharedMemorySize,
                         PROJ_SMEM_BYTES);
    cudaFuncSetAttribute(sim_kernel, cudaFuncAttributeMaxDynamicSharedMemorySize,
                         SIM_SMEM_BYTES);

    pack_kernel<<<8192, 256>>>(pos);
    proj_kernel<<<dim3(128, 2), 256, PROJ_SMEM_BYTES>>>(z_mp, z_sc, W1, b1, W2, b2);
    sim_kernel<<<dim3(128, 64), 256, SIM_SMEM_BYTES>>>();
    finish_kernel<<<128, 256>>>(out);
}